// round 13
// baseline (speedup 1.0000x reference)
#include <cuda_runtime.h>
#include <cuda_bf16.h>

// ---------------- problem constants ----------------
#define BATCH   8
#define HW      112
#define DIM     192
#define HEADS   6
#define HD      32
#define INNER   192
#define MLPD    768
#define WS      7
#define WS2     49
#define NWIN    16
#define TOKENS  (BATCH*HW*HW)        // 100352
#define TOK_IMG (HW*HW)              // 12544

// ---------------- scratch ----------------
__device__ __nv_bfloat16 g_qkv [(size_t)TOKENS*576];
__device__ __nv_bfloat16 g_attn[(size_t)TOKENS*INNER];
__device__ float         g_x2  [(size_t)TOKENS*DIM];
__device__ __nv_bfloat16 g_mlp [(size_t)TOKENS*MLPD];
__device__ __nv_bfloat16 g_wqkvT[576*DIM];     // [N][K]
__device__ __nv_bfloat16 g_woutT[DIM*INNER];
__device__ __nv_bfloat16 g_w1T  [MLPD*DIM];
__device__ __nv_bfloat16 g_w2T  [DIM*MLPD];
__device__ float         g_bias4[4*64*64];     // 4 window classes, masks baked in

// ---------------- helpers ----------------
__device__ __forceinline__ void cp16(void* s, const void* g) {
    unsigned sa = (unsigned)__cvta_generic_to_shared(s);
    asm volatile("cp.async.cg.shared.global [%0], [%1], 16;\n" :: "r"(sa), "l"(g));
}
__device__ __forceinline__ void cp_commit() { asm volatile("cp.async.commit_group;\n"); }
template<int N> __device__ __forceinline__ void cp_wait() {
    asm volatile("cp.async.wait_group %0;\n" :: "n"(N));
}
__device__ __forceinline__ void ldsm4(unsigned* r, const void* p) {
    unsigned a = (unsigned)__cvta_generic_to_shared(p);
    asm volatile("ldmatrix.sync.aligned.m8n8.x4.shared.b16 {%0,%1,%2,%3}, [%4];\n"
        : "=r"(r[0]),"=r"(r[1]),"=r"(r[2]),"=r"(r[3]) : "r"(a));
}
__device__ __forceinline__ void ldsm4t(unsigned* r, const void* p) {
    unsigned a = (unsigned)__cvta_generic_to_shared(p);
    asm volatile("ldmatrix.sync.aligned.m8n8.x4.trans.shared.b16 {%0,%1,%2,%3}, [%4];\n"
        : "=r"(r[0]),"=r"(r[1]),"=r"(r[2]),"=r"(r[3]) : "r"(a));
}
__device__ __forceinline__ void mma16816(float* d, const unsigned* a, const unsigned* b) {
    asm volatile("mma.sync.aligned.m16n8k16.row.col.f32.bf16.bf16.f32 "
        "{%0,%1,%2,%3}, {%4,%5,%6,%7}, {%8,%9}, {%0,%1,%2,%3};\n"
        : "+f"(d[0]),"+f"(d[1]),"+f"(d[2]),"+f"(d[3])
        : "r"(a[0]),"r"(a[1]),"r"(a[2]),"r"(a[3]), "r"(b[0]),"r"(b[1]));
}

// ---------------- weight transpose convert + 4 masked-bias tables ----------------
#define SZ_QKV (576*DIM)
#define SZ_OUT (DIM*INNER)
#define SZ_W1  (MLPD*DIM)
#define SZ_W2  (DIM*MLPD)
#define SZ_ALL (SZ_QKV+SZ_OUT+SZ_W1+SZ_W2)
__global__ void convert_kernel(
    const float* __restrict__ wqkv, const float* __restrict__ wout,
    const float* __restrict__ w1, const float* __restrict__ w2,
    const float* __restrict__ pos,
    __nv_bfloat16* __restrict__ o_qkvT, __nv_bfloat16* __restrict__ o_outT,
    __nv_bfloat16* __restrict__ o_w1T, __nv_bfloat16* __restrict__ o_w2T,
    float* __restrict__ bias4)
{
    int i = blockIdx.x * blockDim.x + threadIdx.x;
    if (i < SZ_QKV) { int n=i/192,k=i%192; o_qkvT[i]=__float2bfloat16(wqkv[k*576+n]); return; }
    i -= SZ_QKV;
    if (i < SZ_OUT) { int n=i/192,k=i%192; o_outT[i]=__float2bfloat16(wout[k*192+n]); return; }
    i -= SZ_OUT;
    if (i < SZ_W1)  { int n=i/192,k=i%192; o_w1T[i]=__float2bfloat16(w1[k*768+n]); return; }
    i -= SZ_W1;
    if (i < SZ_W2)  { int n=i/768,k=i%768; o_w2T[i]=__float2bfloat16(w2[k*192+n]); return; }
    i -= SZ_W2;
    if (i < 4*64*64) {
        int t = i >> 12;                 // window class: bit0=ul (bottom row), bit1=lr (right col)
        int e = i & 4095;
        int r = e >> 6, c = e & 63;
        float v;
        if (c >= WS2) {
            v = -1e9f;                   // pad cols killed unconditionally
        } else if (r >= WS2) {
            v = 0.f;                     // pad rows: value irrelevant (never written)
        } else {
            int ri = r / WS, ci = r % WS, rj = c / WS, cj = c % WS;
            v = pos[(ri - rj + WS - 1) * (2*WS - 1) + (ci - cj + WS - 1)];
            bool ib = (r >= 28), jb = (c >= 28);
            bool i7 = (r % 7) >= 4, j7 = (c % 7) >= 4;
            if ((t & 1) && (ib != jb)) v -= 1e9f;
            if ((t & 2) && (i7 != j7)) v -= 1e9f;
        }
        bias4[i] = v;
    }
}

enum { EPI_QKV = 0, EPI_PROJ = 1, EPI_MLP1 = 2, EPI_MLP2 = 3 };

// ---------------- A-resident GEMM (K=192), 2 CTAs/SM, optional fused LN on A ----------------
#define AST 200
#define ARES_A_BY  (128*AST*2)              // 51200
#define ARES_B_BY  (64*AST*2)               // 25600
#define ARES_SMEM  (ARES_A_BY + 2*ARES_B_BY)  // 102400

template<int EPI, int NC, int LNA, int LNSHIFT>
__global__ void __launch_bounds__(256, 2) gemm_ares(
    const __nv_bfloat16* __restrict__ A, const float* __restrict__ lnSrc,
    const float* __restrict__ lng, const float* __restrict__ lnb,
    const __nv_bfloat16* __restrict__ Bt, int Nfull,
    const float* __restrict__ bias, const float* __restrict__ resid,
    float* __restrict__ outF, __nv_bfloat16* __restrict__ outH)
{
    extern __shared__ __align__(16) unsigned char smem[];
    __nv_bfloat16* As = (__nv_bfloat16*)smem;
    const int tid  = threadIdx.x;
    const int warp = tid >> 5;
    const int lane = tid & 31;
    const int wm   = warp >> 1;
    const int wn   = warp & 1;
    const int row0 = blockIdx.x * 128;
    const int g    = lane >> 3;
    const int r8   = lane & 7;

    // stage B chunk 0 first (overlaps A staging / LN)
    {
        __nv_bfloat16* Bs = (__nv_bfloat16*)(smem + ARES_A_BY);
#pragma unroll
        for (int l = 0; l < 6; l++) {
            int cid = l*256 + tid;
            int rn = cid / 24, c = cid % 24;
            cp16(&Bs[rn*AST + c*8], Bt + (size_t)rn*192 + c*8);
        }
    }

    // stage A
    if (LNA) {
#pragma unroll 4
        for (int rr = 0; rr < 16; rr++) {
            int rl = warp*16 + rr;
            int gr = row0 + rl;
            size_t src;
            if (LNSHIFT) {
                int bq = gr / TOK_IMG;
                int r2 = (gr / HW) % HW;
                int c2 = gr % HW;
                src = (size_t)(bq * TOK_IMG + ((r2 + 3) % HW) * HW + ((c2 + 3) % HW)) * DIM;
            } else {
                src = (size_t)gr * DIM;
            }
            float v[6];
            float s = 0.f, q = 0.f;
#pragma unroll
            for (int k = 0; k < 6; k++) {
                v[k] = __ldg(lnSrc + src + lane + 32*k);
                s += v[k]; q += v[k]*v[k];
            }
#pragma unroll
            for (int o = 16; o > 0; o >>= 1) {
                s += __shfl_xor_sync(0xffffffffu, s, o);
                q += __shfl_xor_sync(0xffffffffu, q, o);
            }
            float mean = s * (1.f/DIM);
            float rstd = rsqrtf(q * (1.f/DIM) - mean*mean + 1e-5f);
#pragma unroll
            for (int k = 0; k < 6; k++) {
                int c = lane + 32*k;
                As[rl*AST + c] = __float2bfloat16((v[k] - mean) * rstd * __ldg(lng + c) + __ldg(lnb + c));
            }
        }
    } else {
#pragma unroll
        for (int l = 0; l < 12; l++) {
            int cid = l*256 + tid;
            int r = cid / 24, c = cid % 24;
            cp16(&As[r*AST + c*8], A + (size_t)(row0 + r)*192 + c*8);
        }
    }
    cp_commit();

    const int lr = lane >> 2;
    const int lc = (lane & 3) * 2;

    for (int ch = 0; ch < NC; ch++) {
        cp_wait<0>();
        __syncthreads();
        if (ch + 1 < NC) {
            __nv_bfloat16* Bn = (__nv_bfloat16*)(smem + ARES_A_BY + ((ch + 1) & 1) * ARES_B_BY);
            const __nv_bfloat16* src = Bt + (size_t)(ch + 1)*64*192;
#pragma unroll
            for (int l = 0; l < 6; l++) {
                int cid = l*256 + tid;
                int rn = cid / 24, c = cid % 24;
                cp16(&Bn[rn*AST + c*8], src + (size_t)rn*192 + c*8);
            }
            cp_commit();
        }
        __nv_bfloat16* Bs = (__nv_bfloat16*)(smem + ARES_A_BY + (ch & 1) * ARES_B_BY);

        float acc[2][4][4];
#pragma unroll
        for (int mt = 0; mt < 2; mt++)
#pragma unroll
            for (int nt = 0; nt < 4; nt++)
                acc[mt][nt][0]=acc[mt][nt][1]=acc[mt][nt][2]=acc[mt][nt][3]=0.f;

#pragma unroll
        for (int kk = 0; kk < 192; kk += 16) {
            unsigned af[2][4];
#pragma unroll
            for (int mt = 0; mt < 2; mt++)
                ldsm4(af[mt], &As[(wm*32 + mt*16 + (g & 1)*8 + r8)*AST + kk + (g >> 1)*8]);
#pragma unroll
            for (int nt16 = 0; nt16 < 2; nt16++) {
                unsigned bf2[4];
                ldsm4(bf2, &Bs[(wn*32 + nt16*16 + (g >> 1)*8 + r8)*AST + kk + (g & 1)*8]);
#pragma unroll
                for (int mt = 0; mt < 2; mt++) {
                    mma16816(acc[mt][nt16*2],     af[mt], bf2);
                    mma16816(acc[mt][nt16*2 + 1], af[mt], bf2 + 2);
                }
            }
        }

        const int cbase = ch*64 + wn*32;
#pragma unroll
        for (int mt = 0; mt < 2; mt++) {
#pragma unroll
            for (int half = 0; half < 2; half++) {
                int gr = row0 + wm*32 + mt*16 + lr + half*8;
                if (EPI == EPI_QKV) {
                    __nv_bfloat16* orow = outH + (size_t)gr*Nfull + cbase;
#pragma unroll
                    for (int nt = 0; nt < 4; nt++) {
                        __nv_bfloat162 pr = __floats2bfloat162_rn(
                            acc[mt][nt][half*2], acc[mt][nt][half*2 + 1]);
                        *(__nv_bfloat162*)(orow + nt*8 + lc) = pr;
                    }
                } else if (EPI == EPI_MLP1) {
                    __nv_bfloat16* orow = outH + (size_t)gr*Nfull + cbase;
#pragma unroll
                    for (int nt = 0; nt < 4; nt++) {
                        float v0 = acc[mt][nt][half*2]     + __ldg(bias + cbase + nt*8 + lc);
                        float v1 = acc[mt][nt][half*2 + 1] + __ldg(bias + cbase + nt*8 + lc + 1);
                        v0 = 0.5f*v0*(1.f + erff(v0*0.7071067811865476f));
                        v1 = 0.5f*v1*(1.f + erff(v1*0.7071067811865476f));
                        *(__nv_bfloat162*)(orow + nt*8 + lc) = __floats2bfloat162_rn(v0, v1);
                    }
                } else { // EPI_PROJ
                    int bq = gr / TOK_IMG;
                    int rr = (gr / HW) % HW;
                    int cc = gr % HW;
                    int drow = bq * TOK_IMG + ((rr + 3) % HW) * HW + ((cc + 3) % HW);
                    float* orow = outF + (size_t)drow*DIM + cbase;
                    const float* rrow = resid + (size_t)drow*DIM + cbase;
#pragma unroll
                    for (int nt = 0; nt < 4; nt++) {
                        float2 rs = *(const float2*)(rrow + nt*8 + lc);
                        float2 ov;
                        ov.x = acc[mt][nt][half*2]     + __ldg(bias + cbase + nt*8 + lc)     + rs.x;
                        ov.y = acc[mt][nt][half*2 + 1] + __ldg(bias + cbase + nt*8 + lc + 1) + rs.y;
                        *(float2*)(orow + nt*8 + lc) = ov;
                    }
                }
            }
        }
    }
}

// ---------------- K-staged GEMM (MLP2, K=768) ----------------
#define GSTRIDE 72
#define STAGE_A  (256*GSTRIDE)
#define STAGE_B  (64*GSTRIDE)
#define STAGE_EL (STAGE_A + STAGE_B)
#define STAGE_BY (STAGE_EL*2)
#define GEMM_SMEM (2*STAGE_BY)

__global__ void __launch_bounds__(256, 2) gemm_mlp2(
    const __nv_bfloat16* __restrict__ A, const __nv_bfloat16* __restrict__ Bt,
    int K,
    const float* __restrict__ bias, const float* __restrict__ resid,
    float* __restrict__ outF)
{
    extern __shared__ __align__(16) unsigned char smem[];
    const int tid  = threadIdx.x;
    const int warp = tid >> 5;
    const int lane = tid & 31;
    const int wm   = warp >> 1;
    const int wn   = warp & 1;
    const int row0 = blockIdx.y * 256;
    const int col0 = blockIdx.x * 64;
    const int g    = lane >> 3;
    const int r8   = lane & 7;

    float acc[4][4][4];
#pragma unroll
    for (int mt = 0; mt < 4; mt++)
#pragma unroll
        for (int nt = 0; nt < 4; nt++)
            acc[mt][nt][0]=acc[mt][nt][1]=acc[mt][nt][2]=acc[mt][nt][3]=0.f;

    auto loadStage = [&](int kb, int s) {
        __nv_bfloat16* As = (__nv_bfloat16*)(smem + (size_t)s * STAGE_BY);
        __nv_bfloat16* Bs = As + STAGE_A;
#pragma unroll
        for (int l = 0; l < 8; l++) {
            int v = tid + l*256;
            int rr = v >> 3, c = (v & 7) * 8;
            cp16(&As[rr*GSTRIDE + c], A + (size_t)(row0 + rr)*K + kb + c);
        }
#pragma unroll
        for (int l = 0; l < 2; l++) {
            int v = tid + l*256;
            int rn = v >> 3, c = (v & 7) * 8;
            cp16(&Bs[rn*GSTRIDE + c], Bt + (size_t)(col0 + rn)*K + kb + c);
        }
        cp_commit();
    };

    const int T = K >> 6;
    loadStage(0, 0);
    for (int t = 0; t < T; t++) {
        cp_wait<0>();
        __syncthreads();
        if (t + 1 < T) loadStage((t + 1) << 6, (t + 1) & 1);
        __nv_bfloat16* As = (__nv_bfloat16*)(smem + (size_t)(t & 1) * STAGE_BY);
        __nv_bfloat16* Bs = As + STAGE_A;
#pragma unroll
        for (int kk = 0; kk < 64; kk += 16) {
            unsigned af[4][4];
#pragma unroll
            for (int mt = 0; mt < 4; mt++)
                ldsm4(af[mt], &As[(wm*64 + mt*16 + (g & 1)*8 + r8)*GSTRIDE + kk + (g >> 1)*8]);
#pragma unroll
            for (int nt16 = 0; nt16 < 2; nt16++) {
                unsigned bf2[4];
                ldsm4(bf2, &Bs[(wn*32 + nt16*16 + (g >> 1)*8 + r8)*GSTRIDE + kk + (g & 1)*8]);
#pragma unroll
                for (int mt = 0; mt < 4; mt++) {
                    mma16816(acc[mt][nt16*2],     af[mt], bf2);
                    mma16816(acc[mt][nt16*2 + 1], af[mt], bf2 + 2);
                }
            }
        }
    }

    const int lr = lane >> 2;
    const int lc = (lane & 3) * 2;
    const int cbase = col0 + wn*32;

#pragma unroll
    for (int mt = 0; mt < 4; mt++) {
#pragma unroll
        for (int half = 0; half < 2; half++) {
            int gr = row0 + wm*64 + mt*16 + lr + half*8;
            float* orow = outF + (size_t)gr*DIM + cbase;
            const float* rrow = resid + (size_t)gr*DIM + cbase;
#pragma unroll
            for (int nt = 0; nt < 4; nt++) {
                float2 rs = *(const float2*)(rrow + nt*8 + lc);
                float2 ov;
                ov.x = acc[mt][nt][half*2]     + __ldg(bias + cbase + nt*8 + lc)     + rs.x;
                ov.y = acc[mt][nt][half*2 + 1] + __ldg(bias + cbase + nt*8 + lc + 1) + rs.y;
                *(float2*)(orow + nt*8 + lc) = ov;
            }
        }
    }
}

// ---------------- window attention: table-lookup softmax ----------------
__global__ void __launch_bounds__(128) attn_kernel(
    const __nv_bfloat16* __restrict__ qkv, const float* __restrict__ bias4,
    __nv_bfloat16* __restrict__ outA)
{
    __shared__ __align__(16) __nv_bfloat16 sQ[64*40];
    __shared__ __align__(16) __nv_bfloat16 sK[64*40];
    __shared__ __align__(16) __nv_bfloat16 sV[64*40];

    int tid = threadIdx.x, w = tid >> 5, lane = tid & 31;
    int h = blockIdx.x, win = blockIdx.y, b = blockIdx.z;
    int wi = win >> 4, wj = win & 15;
    int wclass = ((wi == NWIN-1) ? 1 : 0) | ((wj == NWIN-1) ? 2 : 0);
    int tokbase = (b*HW + wi*WS)*HW + wj*WS;

    // zero pad rows 49..63 of Q, K, V (garbage-free scores; table add is safe)
    uint4 z4 = make_uint4(0,0,0,0);
    {
        __nv_bfloat16* mats[3] = {sQ, sK, sV};
        for (int e = tid; e < 180; e += 128) {
            int m = e / 60, rem = e % 60;
            int rr = 49 + (rem >> 2), ch = rem & 3;
            *(uint4*)&mats[m][rr*40 + ch*8] = z4;
        }
    }
    for (int e = tid; e < 196; e += 128) {
        int i = e >> 2, ch = e & 3;
        int t = tokbase + (i/WS)*HW + (i%WS);
        const __nv_bfloat16* p = qkv + (size_t)t*576 + h*HD + ch*8;
        *(uint4*)&sQ[i*40 + ch*8] = *(const uint4*)(p);
        *(uint4*)&sK[i*40 + ch*8] = *(const uint4*)(p + 192);
        *(uint4*)&sV[i*40 + ch*8] = *(const uint4*)(p + 384);
    }
    __syncthreads();

    int g = lane >> 3, r = lane & 7;

    unsigned qa[2][4];
#pragma unroll
    for (int kt = 0; kt < 2; kt++)
        ldsm4(qa[kt], &sQ[(w*16 + (g & 1)*8 + r)*40 + kt*16 + (g >> 1)*8]);

    float acc[8][4];
#pragma unroll
    for (int t = 0; t < 8; t++) { acc[t][0]=acc[t][1]=acc[t][2]=acc[t][3]=0.f; }
#pragma unroll
    for (int nt = 0; nt < 4; nt++) {
#pragma unroll
        for (int kt = 0; kt < 2; kt++) {
            unsigned bk[4];
            ldsm4(bk, &sK[(nt*16 + (g >> 1)*8 + r)*40 + kt*16 + (g & 1)*8]);
            mma16816(acc[nt*2],     qa[kt], bk);
            mma16816(acc[nt*2 + 1], qa[kt], bk + 2);
        }
    }

    // softmax: single FMA against the precomputed class table
    const float SC = 0.17677669529663689f;
    int q2 = (lane & 3)*2;
    const float* tblBase = bias4 + wclass*4096;
#pragma unroll
    for (int sel = 0; sel < 2; sel++) {
        int i = w*16 + (lane >> 2) + sel*8;
        const float* tbl = tblBase + i*64 + q2;
        float v[16];
        float mx = -1e30f;
#pragma unroll
        for (int t = 0; t < 8; t++) {
            float2 bb = *(const float2*)(tbl + t*8);
            float v0 = fmaf(acc[t][sel*2],     SC, bb.x);
            float v1 = fmaf(acc[t][sel*2 + 1], SC, bb.y);
            v[2*t] = v0; v[2*t + 1] = v1;
            mx = fmaxf(mx, fmaxf(v0, v1));
        }
        mx = fmaxf(mx, __shfl_xor_sync(0xffffffffu, mx, 1));
        mx = fmaxf(mx, __shfl_xor_sync(0xffffffffu, mx, 2));
        float sum = 0.f;
#pragma unroll
        for (int e = 0; e < 16; e++) { float ev = __expf(v[e] - mx); v[e] = ev; sum += ev; }
        sum += __shfl_xor_sync(0xffffffffu, sum, 1);
        sum += __shfl_xor_sync(0xffffffffu, sum, 2);
        float inv = 1.f / sum;
#pragma unroll
        for (int t = 0; t < 8; t++) {
            acc[t][sel*2]     = v[2*t] * inv;
            acc[t][sel*2 + 1] = v[2*t + 1] * inv;
        }
    }

    float o[4][4];
#pragma unroll
    for (int t = 0; t < 4; t++) { o[t][0]=o[t][1]=o[t][2]=o[t][3]=0.f; }
#pragma unroll
    for (int kt = 0; kt < 4; kt++) {
        unsigned pa[4];
        __nv_bfloat162 t0 = __floats2bfloat162_rn(acc[2*kt][0],     acc[2*kt][1]);
        __nv_bfloat162 t1 = __floats2bfloat162_rn(acc[2*kt][2],     acc[2*kt][3]);
        __nv_bfloat162 t2 = __floats2bfloat162_rn(acc[2*kt + 1][0], acc[2*kt + 1][1]);
        __nv_bfloat162 t3 = __floats2bfloat162_rn(acc[2*kt + 1][2], acc[2*kt + 1][3]);
        pa[0] = *(unsigned*)&t0; pa[1] = *(unsigned*)&t1;
        pa[2] = *(unsigned*)&t2; pa[3] = *(unsigned*)&t3;
        unsigned bv[4];
        ldsm4t(bv, &sV[(kt*16 + (g & 1)*8 + r)*40 + (g >> 1)*8]);
        mma16816(o[0], pa, bv);
        mma16816(o[1], pa, bv + 2);
        ldsm4t(bv, &sV[(kt*16 + (g & 1)*8 + r)*40 + 16 + (g >> 1)*8]);
        mma16816(o[2], pa, bv);
        mma16816(o[3], pa, bv + 2);
    }

#pragma unroll
    for (int sel = 0; sel < 2; sel++) {
        int i = w*16 + (lane >> 2) + sel*8;
        if (i < WS2) {
            int tok = tokbase + (i/WS)*HW + (i%WS);
            __nv_bfloat16* po = outA + (size_t)tok*INNER + h*HD + q2;
#pragma unroll
            for (int dt = 0; dt < 4; dt++) {
                __nv_bfloat162 pr = __floats2bfloat162_rn(o[dt][sel*2], o[dt][sel*2 + 1]);
                *(__nv_bfloat162*)(po + dt*8) = pr;
            }
        }
    }
}

// ---------------- launch ----------------
extern "C" void kernel_launch(void* const* d_in, const int* in_sizes, int n_in,
                              void* d_out, int out_size)
{
    const float* x      = (const float*)d_in[0];
    const float* w_qkv  = (const float*)d_in[1];
    const float* w_out  = (const float*)d_in[2];
    const float* b_out  = (const float*)d_in[3];
    const float* pos    = (const float*)d_in[4];
    const float* ln1_g  = (const float*)d_in[5];
    const float* ln1_b  = (const float*)d_in[6];
    const float* ln2_g  = (const float*)d_in[7];
    const float* ln2_b  = (const float*)d_in[8];
    const float* w1     = (const float*)d_in[9];
    const float* b1     = (const float*)d_in[10];
    const float* w2     = (const float*)d_in[11];
    const float* b2     = (const float*)d_in[12];
    float* out = (float*)d_out;

    void *p_qkv, *p_attn, *p_x2, *p_mlp;
    void *p_wqkvT, *p_woutT, *p_w1T, *p_w2T, *p_bias;
    cudaGetSymbolAddress(&p_qkv,  g_qkv);
    cudaGetSymbolAddress(&p_attn, g_attn);
    cudaGetSymbolAddress(&p_x2,   g_x2);
    cudaGetSymbolAddress(&p_mlp,  g_mlp);
    cudaGetSymbolAddress(&p_wqkvT, g_wqkvT);
    cudaGetSymbolAddress(&p_woutT, g_woutT);
    cudaGetSymbolAddress(&p_w1T,   g_w1T);
    cudaGetSymbolAddress(&p_w2T,   g_w2T);
    cudaGetSymbolAddress(&p_bias,  g_bias4);

    static bool attr_done = false;
    if (!attr_done) {
        cudaFuncSetAttribute((const void*)gemm_ares<EPI_QKV, 9, 1, 1>,
                             cudaFuncAttributeMaxDynamicSharedMemorySize, ARES_SMEM);
        cudaFuncSetAttribute((const void*)gemm_ares<EPI_PROJ, 3, 0, 0>,
                             cudaFuncAttributeMaxDynamicSharedMemorySize, ARES_SMEM);
        cudaFuncSetAttribute((const void*)gemm_ares<EPI_MLP1, 12, 1, 0>,
                             cudaFuncAttributeMaxDynamicSharedMemorySize, ARES_SMEM);
        cudaFuncSetAttribute((const void*)gemm_mlp2,
                             cudaFuncAttributeMaxDynamicSharedMemorySize, GEMM_SMEM);
        attr_done = true;
    }

    convert_kernel<<<(SZ_ALL + 4*64*64 + 255)/256, 256>>>(
        w_qkv, w_out, w1, w2, pos,
        (__nv_bfloat16*)p_wqkvT, (__nv_bfloat16*)p_woutT,
        (__nv_bfloat16*)p_w1T, (__nv_bfloat16*)p_w2T, (float*)p_bias);

    // QKV with fused shifted LN1 on A
    gemm_ares<EPI_QKV, 9, 1, 1><<<TOKENS/128, 256, ARES_SMEM>>>(
        nullptr, x, ln1_g, ln1_b,
        (const __nv_bfloat16*)p_wqkvT, 576,
        nullptr, nullptr, nullptr, (__nv_bfloat16*)p_qkv);

    attn_kernel<<<dim3(HEADS, NWIN*NWIN, BATCH), 128>>>(
        (const __nv_bfloat16*)p_qkv, (const float*)p_bias, (__nv_bfloat16*)p_attn);

    // PROJ + back-shift + residual -> x2
    gemm_ares<EPI_PROJ, 3, 0, 0><<<TOKENS/128, 256, ARES_SMEM>>>(
        (const __nv_bfloat16*)p_attn, nullptr, nullptr, nullptr,
        (const __nv_bfloat16*)p_woutT, DIM,
        b_out, x, (float*)p_x2, nullptr);

    // MLP1 with fused LN2 on A + exact GELU
    gemm_ares<EPI_MLP1, 12, 1, 0><<<TOKENS/128, 256, ARES_SMEM>>>(
        nullptr, (const float*)p_x2, ln2_g, ln2_b,
        (const __nv_bfloat16*)p_w1T, MLPD,
        b1, nullptr, nullptr, (__nv_bfloat16*)p_mlp);

    // MLP2 + residual -> out
    gemm_mlp2<<<dim3(DIM/64, TOKENS/256), 256, GEMM_SMEM>>>(
        (const __nv_bfloat16*)p_mlp, (const __nv_bfloat16*)p_w2T, MLPD,
        b2, (const float*)p_x2, out);
}

// round 14
// speedup vs baseline: 1.0891x; 1.0891x over previous
#include <cuda_runtime.h>
#include <cuda_bf16.h>

// ---------------- problem constants ----------------
#define BATCH   8
#define HW      112
#define DIM     192
#define HEADS   6
#define HD      32
#define INNER   192
#define MLPD    768
#define WS      7
#define WS2     49
#define NWIN    16
#define TOKENS  (BATCH*HW*HW)        // 100352
#define TOK_IMG (HW*HW)              // 12544

// ---------------- scratch ----------------
__device__ __nv_bfloat16 g_qkv [(size_t)TOKENS*576];
__device__ __nv_bfloat16 g_attn[(size_t)TOKENS*INNER];
__device__ float         g_x2  [(size_t)TOKENS*DIM];
__device__ __nv_bfloat16 g_mlp [(size_t)TOKENS*MLPD];
__device__ __nv_bfloat16 g_wqkvT[576*DIM];     // [N][K]
__device__ __nv_bfloat16 g_woutT[DIM*INNER];
__device__ __nv_bfloat16 g_w1T  [MLPD*DIM];
__device__ __nv_bfloat16 g_w2T  [DIM*MLPD];
__device__ float         g_bias2[64*64];

// ---------------- helpers ----------------
__device__ __forceinline__ void cp16(void* s, const void* g) {
    unsigned sa = (unsigned)__cvta_generic_to_shared(s);
    asm volatile("cp.async.cg.shared.global [%0], [%1], 16;\n" :: "r"(sa), "l"(g));
}
__device__ __forceinline__ void cp_commit() { asm volatile("cp.async.commit_group;\n"); }
template<int N> __device__ __forceinline__ void cp_wait() {
    asm volatile("cp.async.wait_group %0;\n" :: "n"(N));
}
__device__ __forceinline__ void ldsm4(unsigned* r, const void* p) {
    unsigned a = (unsigned)__cvta_generic_to_shared(p);
    asm volatile("ldmatrix.sync.aligned.m8n8.x4.shared.b16 {%0,%1,%2,%3}, [%4];\n"
        : "=r"(r[0]),"=r"(r[1]),"=r"(r[2]),"=r"(r[3]) : "r"(a));
}
__device__ __forceinline__ void ldsm4t(unsigned* r, const void* p) {
    unsigned a = (unsigned)__cvta_generic_to_shared(p);
    asm volatile("ldmatrix.sync.aligned.m8n8.x4.trans.shared.b16 {%0,%1,%2,%3}, [%4];\n"
        : "=r"(r[0]),"=r"(r[1]),"=r"(r[2]),"=r"(r[3]) : "r"(a));
}
__device__ __forceinline__ void mma16816(float* d, const unsigned* a, const unsigned* b) {
    asm volatile("mma.sync.aligned.m16n8k16.row.col.f32.bf16.bf16.f32 "
        "{%0,%1,%2,%3}, {%4,%5,%6,%7}, {%8,%9}, {%0,%1,%2,%3};\n"
        : "+f"(d[0]),"+f"(d[1]),"+f"(d[2]),"+f"(d[3])
        : "r"(a[0]),"r"(a[1]),"r"(a[2]),"r"(a[3]), "r"(b[0]),"r"(b[1]));
}
__device__ __forceinline__ float gelu_tanh(float x) {
    // tanh-form GELU via HW MUFU.TANH; matches erf-GELU to ~1e-4 abs in our range
    float t = __tanhf(0.7978845608028654f * fmaf(0.044715f * x * x, x, x));
    return 0.5f * x * (1.f + t);
}

// ---------------- weight transpose convert + padded rel-bias ----------------
#define SZ_QKV (576*DIM)
#define SZ_OUT (DIM*INNER)
#define SZ_W1  (MLPD*DIM)
#define SZ_W2  (DIM*MLPD)
#define SZ_ALL (SZ_QKV+SZ_OUT+SZ_W1+SZ_W2)
__global__ void convert_kernel(
    const float* __restrict__ wqkv, const float* __restrict__ wout,
    const float* __restrict__ w1, const float* __restrict__ w2,
    const float* __restrict__ pos,
    __nv_bfloat16* __restrict__ o_qkvT, __nv_bfloat16* __restrict__ o_outT,
    __nv_bfloat16* __restrict__ o_w1T, __nv_bfloat16* __restrict__ o_w2T,
    float* __restrict__ bias2)
{
    int i = blockIdx.x * blockDim.x + threadIdx.x;
    if (i < SZ_QKV) { int n=i/192,k=i%192; o_qkvT[i]=__float2bfloat16(wqkv[k*576+n]); return; }
    i -= SZ_QKV;
    if (i < SZ_OUT) { int n=i/192,k=i%192; o_outT[i]=__float2bfloat16(wout[k*192+n]); return; }
    i -= SZ_OUT;
    if (i < SZ_W1)  { int n=i/192,k=i%192; o_w1T[i]=__float2bfloat16(w1[k*768+n]); return; }
    i -= SZ_W1;
    if (i < SZ_W2)  { int n=i/768,k=i%768; o_w2T[i]=__float2bfloat16(w2[k*192+n]); return; }
    i -= SZ_W2;
    if (i < 64*64) {
        int r = i >> 6, c = i & 63;
        float v = 0.f;
        if (r < WS2 && c < WS2) {
            int ri = r / WS, ci = r % WS, rj = c / WS, cj = c % WS;
            v = pos[(ri - rj + WS - 1) * (2*WS - 1) + (ci - cj + WS - 1)];
        }
        bias2[i] = v;
    }
}

enum { EPI_QKV = 0, EPI_PROJ = 1, EPI_MLP1 = 2, EPI_MLP2 = 3 };

// ---------------- A-resident GEMM (K=192), 2 CTAs/SM, optional fused LN on A ----------------
#define AST 200
#define ARES_A_BY  (128*AST*2)              // 51200
#define ARES_B_BY  (64*AST*2)               // 25600
#define ARES_SMEM  (ARES_A_BY + 2*ARES_B_BY)  // 102400

template<int EPI, int NC, int LNA, int LNSHIFT>
__global__ void __launch_bounds__(256, 2) gemm_ares(
    const __nv_bfloat16* __restrict__ A, const float* __restrict__ lnSrc,
    const float* __restrict__ lng, const float* __restrict__ lnb,
    const __nv_bfloat16* __restrict__ Bt, int Nfull,
    const float* __restrict__ bias, const float* __restrict__ resid,
    float* __restrict__ outF, __nv_bfloat16* __restrict__ outH)
{
    extern __shared__ __align__(16) unsigned char smem[];
    __nv_bfloat16* As = (__nv_bfloat16*)smem;
    const int tid  = threadIdx.x;
    const int warp = tid >> 5;
    const int lane = tid & 31;
    const int wm   = warp >> 1;
    const int wn   = warp & 1;
    const int row0 = blockIdx.x * 128;
    const int g    = lane >> 3;
    const int r8   = lane & 7;

    // stage B chunk 0 first (overlaps A staging / LN)
    {
        __nv_bfloat16* Bs = (__nv_bfloat16*)(smem + ARES_A_BY);
#pragma unroll
        for (int l = 0; l < 6; l++) {
            int cid = l*256 + tid;
            int rn = cid / 24, c = cid % 24;
            cp16(&Bs[rn*AST + c*8], Bt + (size_t)rn*192 + c*8);
        }
    }

    // stage A
    if (LNA) {
#pragma unroll 4
        for (int rr = 0; rr < 16; rr++) {
            int rl = warp*16 + rr;
            int gr = row0 + rl;
            size_t src;
            if (LNSHIFT) {
                int bq = gr / TOK_IMG;
                int r2 = (gr / HW) % HW;
                int c2 = gr % HW;
                src = (size_t)(bq * TOK_IMG + ((r2 + 3) % HW) * HW + ((c2 + 3) % HW)) * DIM;
            } else {
                src = (size_t)gr * DIM;
            }
            float v[6];
            float s = 0.f, q = 0.f;
#pragma unroll
            for (int k = 0; k < 6; k++) {
                v[k] = __ldg(lnSrc + src + lane + 32*k);
                s += v[k]; q += v[k]*v[k];
            }
#pragma unroll
            for (int o = 16; o > 0; o >>= 1) {
                s += __shfl_xor_sync(0xffffffffu, s, o);
                q += __shfl_xor_sync(0xffffffffu, q, o);
            }
            float mean = s * (1.f/DIM);
            float rstd = rsqrtf(q * (1.f/DIM) - mean*mean + 1e-5f);
#pragma unroll
            for (int k = 0; k < 6; k++) {
                int c = lane + 32*k;
                As[rl*AST + c] = __float2bfloat16((v[k] - mean) * rstd * __ldg(lng + c) + __ldg(lnb + c));
            }
        }
    } else {
#pragma unroll
        for (int l = 0; l < 12; l++) {
            int cid = l*256 + tid;
            int r = cid / 24, c = cid % 24;
            cp16(&As[r*AST + c*8], A + (size_t)(row0 + r)*192 + c*8);
        }
    }
    cp_commit();

    const int lr = lane >> 2;
    const int lc = (lane & 3) * 2;

    for (int ch = 0; ch < NC; ch++) {
        cp_wait<0>();
        __syncthreads();
        if (ch + 1 < NC) {
            __nv_bfloat16* Bn = (__nv_bfloat16*)(smem + ARES_A_BY + ((ch + 1) & 1) * ARES_B_BY);
            const __nv_bfloat16* src = Bt + (size_t)(ch + 1)*64*192;
#pragma unroll
            for (int l = 0; l < 6; l++) {
                int cid = l*256 + tid;
                int rn = cid / 24, c = cid % 24;
                cp16(&Bn[rn*AST + c*8], src + (size_t)rn*192 + c*8);
            }
            cp_commit();
        }
        __nv_bfloat16* Bs = (__nv_bfloat16*)(smem + ARES_A_BY + (ch & 1) * ARES_B_BY);

        float acc[2][4][4];
#pragma unroll
        for (int mt = 0; mt < 2; mt++)
#pragma unroll
            for (int nt = 0; nt < 4; nt++)
                acc[mt][nt][0]=acc[mt][nt][1]=acc[mt][nt][2]=acc[mt][nt][3]=0.f;

#pragma unroll
        for (int kk = 0; kk < 192; kk += 16) {
            unsigned af[2][4];
#pragma unroll
            for (int mt = 0; mt < 2; mt++)
                ldsm4(af[mt], &As[(wm*32 + mt*16 + (g & 1)*8 + r8)*AST + kk + (g >> 1)*8]);
#pragma unroll
            for (int nt16 = 0; nt16 < 2; nt16++) {
                unsigned bf2[4];
                ldsm4(bf2, &Bs[(wn*32 + nt16*16 + (g >> 1)*8 + r8)*AST + kk + (g & 1)*8]);
#pragma unroll
                for (int mt = 0; mt < 2; mt++) {
                    mma16816(acc[mt][nt16*2],     af[mt], bf2);
                    mma16816(acc[mt][nt16*2 + 1], af[mt], bf2 + 2);
                }
            }
        }

        const int cbase = ch*64 + wn*32;
#pragma unroll
        for (int mt = 0; mt < 2; mt++) {
#pragma unroll
            for (int half = 0; half < 2; half++) {
                int gr = row0 + wm*32 + mt*16 + lr + half*8;
                if (EPI == EPI_QKV) {
                    __nv_bfloat16* orow = outH + (size_t)gr*Nfull + cbase;
#pragma unroll
                    for (int nt = 0; nt < 4; nt++) {
                        __nv_bfloat162 pr = __floats2bfloat162_rn(
                            acc[mt][nt][half*2], acc[mt][nt][half*2 + 1]);
                        *(__nv_bfloat162*)(orow + nt*8 + lc) = pr;
                    }
                } else if (EPI == EPI_MLP1) {
                    __nv_bfloat16* orow = outH + (size_t)gr*Nfull + cbase;
#pragma unroll
                    for (int nt = 0; nt < 4; nt++) {
                        float v0 = acc[mt][nt][half*2]     + __ldg(bias + cbase + nt*8 + lc);
                        float v1 = acc[mt][nt][half*2 + 1] + __ldg(bias + cbase + nt*8 + lc + 1);
                        v0 = gelu_tanh(v0);
                        v1 = gelu_tanh(v1);
                        *(__nv_bfloat162*)(orow + nt*8 + lc) = __floats2bfloat162_rn(v0, v1);
                    }
                } else { // EPI_PROJ
                    int bq = gr / TOK_IMG;
                    int rr = (gr / HW) % HW;
                    int cc = gr % HW;
                    int drow = bq * TOK_IMG + ((rr + 3) % HW) * HW + ((cc + 3) % HW);
                    float* orow = outF + (size_t)drow*DIM + cbase;
                    const float* rrow = resid + (size_t)drow*DIM + cbase;
#pragma unroll
                    for (int nt = 0; nt < 4; nt++) {
                        float2 rs = *(const float2*)(rrow + nt*8 + lc);
                        float2 ov;
                        ov.x = acc[mt][nt][half*2]     + __ldg(bias + cbase + nt*8 + lc)     + rs.x;
                        ov.y = acc[mt][nt][half*2 + 1] + __ldg(bias + cbase + nt*8 + lc + 1) + rs.y;
                        *(float2*)(orow + nt*8 + lc) = ov;
                    }
                }
            }
        }
    }
}

// ---------------- K-staged GEMM (MLP2, K=768) ----------------
#define GSTRIDE 72
#define STAGE_A  (256*GSTRIDE)
#define STAGE_B  (64*GSTRIDE)
#define STAGE_EL (STAGE_A + STAGE_B)
#define STAGE_BY (STAGE_EL*2)
#define GEMM_SMEM (2*STAGE_BY)

__global__ void __launch_bounds__(256, 2) gemm_mlp2(
    const __nv_bfloat16* __restrict__ A, const __nv_bfloat16* __restrict__ Bt,
    int K,
    const float* __restrict__ bias, const float* __restrict__ resid,
    float* __restrict__ outF)
{
    extern __shared__ __align__(16) unsigned char smem[];
    const int tid  = threadIdx.x;
    const int warp = tid >> 5;
    const int lane = tid & 31;
    const int wm   = warp >> 1;
    const int wn   = warp & 1;
    const int row0 = blockIdx.y * 256;
    const int col0 = blockIdx.x * 64;
    const int g    = lane >> 3;
    const int r8   = lane & 7;

    float acc[4][4][4];
#pragma unroll
    for (int mt = 0; mt < 4; mt++)
#pragma unroll
        for (int nt = 0; nt < 4; nt++)
            acc[mt][nt][0]=acc[mt][nt][1]=acc[mt][nt][2]=acc[mt][nt][3]=0.f;

    auto loadStage = [&](int kb, int s) {
        __nv_bfloat16* As = (__nv_bfloat16*)(smem + (size_t)s * STAGE_BY);
        __nv_bfloat16* Bs = As + STAGE_A;
#pragma unroll
        for (int l = 0; l < 8; l++) {
            int v = tid + l*256;
            int rr = v >> 3, c = (v & 7) * 8;
            cp16(&As[rr*GSTRIDE + c], A + (size_t)(row0 + rr)*K + kb + c);
        }
#pragma unroll
        for (int l = 0; l < 2; l++) {
            int v = tid + l*256;
            int rn = v >> 3, c = (v & 7) * 8;
            cp16(&Bs[rn*GSTRIDE + c], Bt + (size_t)(col0 + rn)*K + kb + c);
        }
        cp_commit();
    };

    const int T = K >> 6;
    loadStage(0, 0);
    for (int t = 0; t < T; t++) {
        cp_wait<0>();
        __syncthreads();
        if (t + 1 < T) loadStage((t + 1) << 6, (t + 1) & 1);
        __nv_bfloat16* As = (__nv_bfloat16*)(smem + (size_t)(t & 1) * STAGE_BY);
        __nv_bfloat16* Bs = As + STAGE_A;
#pragma unroll
        for (int kk = 0; kk < 64; kk += 16) {
            unsigned af[4][4];
#pragma unroll
            for (int mt = 0; mt < 4; mt++)
                ldsm4(af[mt], &As[(wm*64 + mt*16 + (g & 1)*8 + r8)*GSTRIDE + kk + (g >> 1)*8]);
#pragma unroll
            for (int nt16 = 0; nt16 < 2; nt16++) {
                unsigned bf2[4];
                ldsm4(bf2, &Bs[(wn*32 + nt16*16 + (g >> 1)*8 + r8)*GSTRIDE + kk + (g & 1)*8]);
#pragma unroll
                for (int mt = 0; mt < 4; mt++) {
                    mma16816(acc[mt][nt16*2],     af[mt], bf2);
                    mma16816(acc[mt][nt16*2 + 1], af[mt], bf2 + 2);
                }
            }
        }
    }

    const int lr = lane >> 2;
    const int lc = (lane & 3) * 2;
    const int cbase = col0 + wn*32;

#pragma unroll
    for (int mt = 0; mt < 4; mt++) {
#pragma unroll
        for (int half = 0; half < 2; half++) {
            int gr = row0 + wm*64 + mt*16 + lr + half*8;
            float* orow = outF + (size_t)gr*DIM + cbase;
            const float* rrow = resid + (size_t)gr*DIM + cbase;
#pragma unroll
            for (int nt = 0; nt < 4; nt++) {
                float2 rs = *(const float2*)(rrow + nt*8 + lc);
                float2 ov;
                ov.x = acc[mt][nt][half*2]     + __ldg(bias + cbase + nt*8 + lc)     + rs.x;
                ov.y = acc[mt][nt][half*2 + 1] + __ldg(bias + cbase + nt*8 + lc + 1) + rs.y;
                *(float2*)(orow + nt*8 + lc) = ov;
            }
        }
    }
}

// ---------------- window attention (register-resident mma.sync, R12-exact) ----------------
__global__ void __launch_bounds__(128) attn_kernel(
    const __nv_bfloat16* __restrict__ qkv, const float* __restrict__ bias2,
    __nv_bfloat16* __restrict__ outA)
{
    __shared__ __align__(16) __nv_bfloat16 sQ[64*40];
    __shared__ __align__(16) __nv_bfloat16 sK[64*40];
    __shared__ __align__(16) __nv_bfloat16 sV[64*40];

    int tid = threadIdx.x, w = tid >> 5, lane = tid & 31;
    int h = blockIdx.x, win = blockIdx.y, b = blockIdx.z;
    int wi = win >> 4, wj = win & 15;
    bool mul = (wi == NWIN-1), mlr = (wj == NWIN-1);
    int tokbase = (b*HW + wi*WS)*HW + wj*WS;

    uint4 z4 = make_uint4(0,0,0,0);
    for (int e = tid; e < 60; e += 128) {
        int rr = 49 + (e >> 2), ch = e & 3;
        *(uint4*)&sV[rr*40 + ch*8] = z4;
    }
    for (int e = tid; e < 196; e += 128) {
        int i = e >> 2, ch = e & 3;
        int t = tokbase + (i/WS)*HW + (i%WS);
        const __nv_bfloat16* p = qkv + (size_t)t*576 + h*HD + ch*8;
        *(uint4*)&sQ[i*40 + ch*8] = *(const uint4*)(p);
        *(uint4*)&sK[i*40 + ch*8] = *(const uint4*)(p + 192);
        *(uint4*)&sV[i*40 + ch*8] = *(const uint4*)(p + 384);
    }
    __syncthreads();

    int g = lane >> 3, r = lane & 7;

    unsigned qa[2][4];
#pragma unroll
    for (int kt = 0; kt < 2; kt++)
        ldsm4(qa[kt], &sQ[(w*16 + (g & 1)*8 + r)*40 + kt*16 + (g >> 1)*8]);

    float acc[8][4];
#pragma unroll
    for (int t = 0; t < 8; t++) { acc[t][0]=acc[t][1]=acc[t][2]=acc[t][3]=0.f; }
#pragma unroll
    for (int nt = 0; nt < 4; nt++) {
#pragma unroll
        for (int kt = 0; kt < 2; kt++) {
            unsigned bk[4];
            ldsm4(bk, &sK[(nt*16 + (g >> 1)*8 + r)*40 + kt*16 + (g & 1)*8]);
            mma16816(acc[nt*2],     qa[kt], bk);
            mma16816(acc[nt*2 + 1], qa[kt], bk + 2);
        }
    }

    const float SC = 0.17677669529663689f;
    int q2 = (lane & 3)*2;
    bool jb[16], j7[16], jp[16];
#pragma unroll
    for (int e = 0; e < 16; e++) {
        int j = (e >> 1)*8 + q2 + (e & 1);
        jb[e] = (j >= 28); j7[e] = ((j % 7) >= 4); jp[e] = (j >= WS2);
    }
#pragma unroll
    for (int sel = 0; sel < 2; sel++) {
        int i = w*16 + (lane >> 2) + sel*8;
        bool ib = (i >= 28), i7 = ((i % 7) >= 4);
        float v[16];
        float mx = -1e30f;
#pragma unroll
        for (int t = 0; t < 8; t++) {
            float2 bb = *(const float2*)&bias2[i*64 + t*8 + q2];
            float v0 = fmaf(acc[t][sel*2],     SC, bb.x);
            float v1 = fmaf(acc[t][sel*2 + 1], SC, bb.y);
            if (mul && (ib != jb[2*t]))     v0 -= 1e9f;
            if (mlr && (i7 != j7[2*t]))     v0 -= 1e9f;
            if (mul && (ib != jb[2*t + 1])) v1 -= 1e9f;
            if (mlr && (i7 != j7[2*t + 1])) v1 -= 1e9f;
            if (jp[2*t])     v0 = -1e9f;
            if (jp[2*t + 1]) v1 = -1e9f;
            v[2*t] = v0; v[2*t + 1] = v1;
            mx = fmaxf(mx, fmaxf(v0, v1));
        }
        mx = fmaxf(mx, __shfl_xor_sync(0xffffffffu, mx, 1));
        mx = fmaxf(mx, __shfl_xor_sync(0xffffffffu, mx, 2));
        float sum = 0.f;
#pragma unroll
        for (int e = 0; e < 16; e++) { float ev = __expf(v[e] - mx); v[e] = ev; sum += ev; }
        sum += __shfl_xor_sync(0xffffffffu, sum, 1);
        sum += __shfl_xor_sync(0xffffffffu, sum, 2);
        float inv = 1.f / sum;
#pragma unroll
        for (int t = 0; t < 8; t++) {
            acc[t][sel*2]     = v[2*t] * inv;
            acc[t][sel*2 + 1] = v[2*t + 1] * inv;
        }
    }

    float o[4][4];
#pragma unroll
    for (int t = 0; t < 4; t++) { o[t][0]=o[t][1]=o[t][2]=o[t][3]=0.f; }
#pragma unroll
    for (int kt = 0; kt < 4; kt++) {
        unsigned pa[4];
        __nv_bfloat162 t0 = __floats2bfloat162_rn(acc[2*kt][0],     acc[2*kt][1]);
        __nv_bfloat162 t1 = __floats2bfloat162_rn(acc[2*kt][2],     acc[2*kt][3]);
        __nv_bfloat162 t2 = __floats2bfloat162_rn(acc[2*kt + 1][0], acc[2*kt + 1][1]);
        __nv_bfloat162 t3 = __floats2bfloat162_rn(acc[2*kt + 1][2], acc[2*kt + 1][3]);
        pa[0] = *(unsigned*)&t0; pa[1] = *(unsigned*)&t1;
        pa[2] = *(unsigned*)&t2; pa[3] = *(unsigned*)&t3;
        unsigned bv[4];
        ldsm4t(bv, &sV[(kt*16 + (g & 1)*8 + r)*40 + (g >> 1)*8]);
        mma16816(o[0], pa, bv);
        mma16816(o[1], pa, bv + 2);
        ldsm4t(bv, &sV[(kt*16 + (g & 1)*8 + r)*40 + 16 + (g >> 1)*8]);
        mma16816(o[2], pa, bv);
        mma16816(o[3], pa, bv + 2);
    }

#pragma unroll
    for (int sel = 0; sel < 2; sel++) {
        int i = w*16 + (lane >> 2) + sel*8;
        if (i < WS2) {
            int tok = tokbase + (i/WS)*HW + (i%WS);
            __nv_bfloat16* po = outA + (size_t)tok*INNER + h*HD + q2;
#pragma unroll
            for (int dt = 0; dt < 4; dt++) {
                __nv_bfloat162 pr = __floats2bfloat162_rn(o[dt][sel*2], o[dt][sel*2 + 1]);
                *(__nv_bfloat162*)(po + dt*8) = pr;
            }
        }
    }
}

// ---------------- launch ----------------
extern "C" void kernel_launch(void* const* d_in, const int* in_sizes, int n_in,
                              void* d_out, int out_size)
{
    const float* x      = (const float*)d_in[0];
    const float* w_qkv  = (const float*)d_in[1];
    const float* w_out  = (const float*)d_in[2];
    const float* b_out  = (const float*)d_in[3];
    const float* pos    = (const float*)d_in[4];
    const float* ln1_g  = (const float*)d_in[5];
    const float* ln1_b  = (const float*)d_in[6];
    const float* ln2_g  = (const float*)d_in[7];
    const float* ln2_b  = (const float*)d_in[8];
    const float* w1     = (const float*)d_in[9];
    const float* b1     = (const float*)d_in[10];
    const float* w2     = (const float*)d_in[11];
    const float* b2     = (const float*)d_in[12];
    float* out = (float*)d_out;

    void *p_qkv, *p_attn, *p_x2, *p_mlp;
    void *p_wqkvT, *p_woutT, *p_w1T, *p_w2T, *p_bias;
    cudaGetSymbolAddress(&p_qkv,  g_qkv);
    cudaGetSymbolAddress(&p_attn, g_attn);
    cudaGetSymbolAddress(&p_x2,   g_x2);
    cudaGetSymbolAddress(&p_mlp,  g_mlp);
    cudaGetSymbolAddress(&p_wqkvT, g_wqkvT);
    cudaGetSymbolAddress(&p_woutT, g_woutT);
    cudaGetSymbolAddress(&p_w1T,   g_w1T);
    cudaGetSymbolAddress(&p_w2T,   g_w2T);
    cudaGetSymbolAddress(&p_bias,  g_bias2);

    static bool attr_done = false;
    if (!attr_done) {
        cudaFuncSetAttribute((const void*)gemm_ares<EPI_QKV, 9, 1, 1>,
                             cudaFuncAttributeMaxDynamicSharedMemorySize, ARES_SMEM);
        cudaFuncSetAttribute((const void*)gemm_ares<EPI_PROJ, 3, 0, 0>,
                             cudaFuncAttributeMaxDynamicSharedMemorySize, ARES_SMEM);
        cudaFuncSetAttribute((const void*)gemm_ares<EPI_MLP1, 12, 1, 0>,
                             cudaFuncAttributeMaxDynamicSharedMemorySize, ARES_SMEM);
        cudaFuncSetAttribute((const void*)gemm_mlp2,
                             cudaFuncAttributeMaxDynamicSharedMemorySize, GEMM_SMEM);
        attr_done = true;
    }

    convert_kernel<<<(SZ_ALL + 64*64 + 255)/256, 256>>>(
        w_qkv, w_out, w1, w2, pos,
        (__nv_bfloat16*)p_wqkvT, (__nv_bfloat16*)p_woutT,
        (__nv_bfloat16*)p_w1T, (__nv_bfloat16*)p_w2T, (float*)p_bias);

    // QKV with fused shifted LN1 on A
    gemm_ares<EPI_QKV, 9, 1, 1><<<TOKENS/128, 256, ARES_SMEM>>>(
        nullptr, x, ln1_g, ln1_b,
        (const __nv_bfloat16*)p_wqkvT, 576,
        nullptr, nullptr, nullptr, (__nv_bfloat16*)p_qkv);

    attn_kernel<<<dim3(HEADS, NWIN*NWIN, BATCH), 128>>>(
        (const __nv_bfloat16*)p_qkv, (const float*)p_bias, (__nv_bfloat16*)p_attn);

    // PROJ + back-shift + residual -> x2
    gemm_ares<EPI_PROJ, 3, 0, 0><<<TOKENS/128, 256, ARES_SMEM>>>(
        (const __nv_bfloat16*)p_attn, nullptr, nullptr, nullptr,
        (const __nv_bfloat16*)p_woutT, DIM,
        b_out, x, (float*)p_x2, nullptr);

    // MLP1 with fused LN2 on A + tanh-GELU
    gemm_ares<EPI_MLP1, 12, 1, 0><<<TOKENS/128, 256, ARES_SMEM>>>(
        nullptr, (const float*)p_x2, ln2_g, ln2_b,
        (const __nv_bfloat16*)p_w1T, MLPD,
        b1, nullptr, nullptr, (__nv_bfloat16*)p_mlp);

    // MLP2 + residual -> out
    gemm_mlp2<<<dim3(DIM/64, TOKENS/256), 256, GEMM_SMEM>>>(
        (const __nv_bfloat16*)p_mlp, (const __nv_bfloat16*)p_w2T, MLPD,
        b2, (const float*)p_x2, out);
}

// round 15
// speedup vs baseline: 1.1113x; 1.0204x over previous
#include <cuda_runtime.h>
#include <cuda_bf16.h>

// ---------------- problem constants ----------------
#define BATCH   8
#define HW      112
#define DIM     192
#define HEADS   6
#define HD      32
#define INNER   192
#define MLPD    768
#define WS      7
#define WS2     49
#define NWIN    16
#define TOKENS  (BATCH*HW*HW)        // 100352
#define TOK_IMG (HW*HW)              // 12544

// ---------------- scratch ----------------
__device__ __nv_bfloat16 g_qkv [(size_t)TOKENS*576];
__device__ __nv_bfloat16 g_attn[(size_t)TOKENS*INNER];
__device__ float         g_x2  [(size_t)TOKENS*DIM];
__device__ __nv_bfloat16 g_mlp [(size_t)TOKENS*MLPD];
__device__ __nv_bfloat16 g_wqkvT[576*DIM];     // [N][K]
__device__ __nv_bfloat16 g_woutT[DIM*INNER];
__device__ __nv_bfloat16 g_w1T  [MLPD*DIM];
__device__ __nv_bfloat16 g_w2T  [DIM*MLPD];
__device__ float         g_bias2[64*64];

// ---------------- helpers ----------------
__device__ __forceinline__ void cp16(void* s, const void* g) {
    unsigned sa = (unsigned)__cvta_generic_to_shared(s);
    asm volatile("cp.async.cg.shared.global [%0], [%1], 16;\n" :: "r"(sa), "l"(g));
}
__device__ __forceinline__ void cp_commit() { asm volatile("cp.async.commit_group;\n"); }
template<int N> __device__ __forceinline__ void cp_wait() {
    asm volatile("cp.async.wait_group %0;\n" :: "n"(N));
}
__device__ __forceinline__ void ldsm4(unsigned* r, const void* p) {
    unsigned a = (unsigned)__cvta_generic_to_shared(p);
    asm volatile("ldmatrix.sync.aligned.m8n8.x4.shared.b16 {%0,%1,%2,%3}, [%4];\n"
        : "=r"(r[0]),"=r"(r[1]),"=r"(r[2]),"=r"(r[3]) : "r"(a));
}
__device__ __forceinline__ void ldsm4t(unsigned* r, const void* p) {
    unsigned a = (unsigned)__cvta_generic_to_shared(p);
    asm volatile("ldmatrix.sync.aligned.m8n8.x4.trans.shared.b16 {%0,%1,%2,%3}, [%4];\n"
        : "=r"(r[0]),"=r"(r[1]),"=r"(r[2]),"=r"(r[3]) : "r"(a));
}
__device__ __forceinline__ void mma16816(float* d, const unsigned* a, const unsigned* b) {
    asm volatile("mma.sync.aligned.m16n8k16.row.col.f32.bf16.bf16.f32 "
        "{%0,%1,%2,%3}, {%4,%5,%6,%7}, {%8,%9}, {%0,%1,%2,%3};\n"
        : "+f"(d[0]),"+f"(d[1]),"+f"(d[2]),"+f"(d[3])
        : "r"(a[0]),"r"(a[1]),"r"(a[2]),"r"(a[3]), "r"(b[0]),"r"(b[1]));
}
__device__ __forceinline__ float gelu_tanh(float x) {
    float t = __tanhf(0.7978845608028654f * fmaf(0.044715f * x * x, x, x));
    return 0.5f * x * (1.f + t);
}

// ---------------- coalesced transpose-convert + rel-bias ----------------
// 32x32 smem tiles; blocks partitioned across the 4 weight matrices + bias table.
// wqkv: 18x6=108 tiles, wout: 6x6=36, w1: 24x6=144, w2: 6x24=144, bias: 16 blocks.
__global__ void __launch_bounds__(256) convert_kernel(
    const float* __restrict__ wqkv, const float* __restrict__ wout,
    const float* __restrict__ w1, const float* __restrict__ w2,
    const float* __restrict__ pos,
    __nv_bfloat16* __restrict__ o_qkvT, __nv_bfloat16* __restrict__ o_outT,
    __nv_bfloat16* __restrict__ o_w1T, __nv_bfloat16* __restrict__ o_w2T,
    float* __restrict__ bias2)
{
    __shared__ float tile[32][33];
    int bid = blockIdx.x;
    const float* src; __nv_bfloat16* dst; int K, N, tid0;
    if (bid < 108)      { src = wqkv; dst = o_qkvT; K = 192; N = 576; tid0 = bid; }
    else if (bid < 144) { src = wout; dst = o_outT; K = 192; N = 192; tid0 = bid - 108; }
    else if (bid < 288) { src = w1;   dst = o_w1T;  K = 192; N = 768; tid0 = bid - 144; }
    else if (bid < 432) { src = w2;   dst = o_w2T;  K = 768; N = 192; tid0 = bid - 288; }
    else {
        // bias table: 16 blocks x 256 = 4096 entries
        int i = (bid - 432) * 256 + threadIdx.x;
        int r = i >> 6, c = i & 63;
        float v = 0.f;
        if (r < WS2 && c < WS2) {
            int ri = r / WS, ci = r % WS, rj = c / WS, cj = c % WS;
            v = pos[(ri - rj + WS - 1) * (2*WS - 1) + (ci - cj + WS - 1)];
        }
        bias2[i] = v;
        return;
    }
    int ntiles_n = N >> 5;
    int n0 = (tid0 % ntiles_n) * 32;
    int k0 = (tid0 / ntiles_n) * 32;
    int tc = threadIdx.x & 31, tr = threadIdx.x >> 5;   // 32x8
#pragma unroll
    for (int rr = 0; rr < 4; rr++) {
        int r = tr + rr*8;
        tile[r][tc] = src[(size_t)(k0 + r)*N + n0 + tc];   // coalesced over n
    }
    __syncthreads();
#pragma unroll
    for (int rr = 0; rr < 4; rr++) {
        int r = tr + rr*8;
        dst[(size_t)(n0 + r)*K + k0 + tc] = __float2bfloat16(tile[tc][r]);  // coalesced over k
    }
}

enum { EPI_QKV = 0, EPI_PROJ = 1, EPI_MLP1 = 2, EPI_MLP2 = 3 };

// ---------------- A-resident GEMM (K=192), 2 CTAs/SM, optional fused LN on A ----------------
#define AST 200
#define ARES_A_BY  (128*AST*2)              // 51200
#define ARES_B_BY  (64*AST*2)               // 25600
#define ARES_SMEM  (ARES_A_BY + 2*ARES_B_BY)  // 102400

template<int EPI, int NC, int LNA, int LNSHIFT>
__global__ void __launch_bounds__(256, 2) gemm_ares(
    const __nv_bfloat16* __restrict__ A, const float* __restrict__ lnSrc,
    const float* __restrict__ lng, const float* __restrict__ lnb,
    const __nv_bfloat16* __restrict__ Bt, int Nfull,
    const float* __restrict__ bias, const float* __restrict__ resid,
    float* __restrict__ outF, __nv_bfloat16* __restrict__ outH)
{
    extern __shared__ __align__(16) unsigned char smem[];
    __nv_bfloat16* As = (__nv_bfloat16*)smem;
    const int tid  = threadIdx.x;
    const int warp = tid >> 5;
    const int lane = tid & 31;
    const int wm   = warp >> 1;
    const int wn   = warp & 1;
    const int row0 = blockIdx.x * 128;
    const int g    = lane >> 3;
    const int r8   = lane & 7;

    // stage B chunk 0 first (overlaps A staging / LN)
    {
        __nv_bfloat16* Bs = (__nv_bfloat16*)(smem + ARES_A_BY);
#pragma unroll
        for (int l = 0; l < 6; l++) {
            int cid = l*256 + tid;
            int rn = cid / 24, c = cid % 24;
            cp16(&Bs[rn*AST + c*8], Bt + (size_t)rn*192 + c*8);
        }
    }

    // stage A
    if (LNA) {
#pragma unroll 4
        for (int rr = 0; rr < 16; rr++) {
            int rl = warp*16 + rr;
            int gr = row0 + rl;
            size_t src;
            if (LNSHIFT) {
                int bq = gr / TOK_IMG;
                int r2 = (gr / HW) % HW;
                int c2 = gr % HW;
                src = (size_t)(bq * TOK_IMG + ((r2 + 3) % HW) * HW + ((c2 + 3) % HW)) * DIM;
            } else {
                src = (size_t)gr * DIM;
            }
            float v[6];
            float s = 0.f, q = 0.f;
#pragma unroll
            for (int k = 0; k < 6; k++) {
                v[k] = __ldg(lnSrc + src + lane + 32*k);
                s += v[k]; q += v[k]*v[k];
            }
#pragma unroll
            for (int o = 16; o > 0; o >>= 1) {
                s += __shfl_xor_sync(0xffffffffu, s, o);
                q += __shfl_xor_sync(0xffffffffu, q, o);
            }
            float mean = s * (1.f/DIM);
            float rstd = rsqrtf(q * (1.f/DIM) - mean*mean + 1e-5f);
#pragma unroll
            for (int k = 0; k < 6; k++) {
                int c = lane + 32*k;
                As[rl*AST + c] = __float2bfloat16((v[k] - mean) * rstd * __ldg(lng + c) + __ldg(lnb + c));
            }
        }
    } else {
#pragma unroll
        for (int l = 0; l < 12; l++) {
            int cid = l*256 + tid;
            int r = cid / 24, c = cid % 24;
            cp16(&As[r*AST + c*8], A + (size_t)(row0 + r)*192 + c*8);
        }
    }
    cp_commit();

    const int lr = lane >> 2;
    const int lc = (lane & 3) * 2;

    for (int ch = 0; ch < NC; ch++) {
        cp_wait<0>();
        __syncthreads();
        if (ch + 1 < NC) {
            __nv_bfloat16* Bn = (__nv_bfloat16*)(smem + ARES_A_BY + ((ch + 1) & 1) * ARES_B_BY);
            const __nv_bfloat16* src = Bt + (size_t)(ch + 1)*64*192;
#pragma unroll
            for (int l = 0; l < 6; l++) {
                int cid = l*256 + tid;
                int rn = cid / 24, c = cid % 24;
                cp16(&Bn[rn*AST + c*8], src + (size_t)rn*192 + c*8);
            }
            cp_commit();
        }
        __nv_bfloat16* Bs = (__nv_bfloat16*)(smem + ARES_A_BY + (ch & 1) * ARES_B_BY);

        float acc[2][4][4];
#pragma unroll
        for (int mt = 0; mt < 2; mt++)
#pragma unroll
            for (int nt = 0; nt < 4; nt++)
                acc[mt][nt][0]=acc[mt][nt][1]=acc[mt][nt][2]=acc[mt][nt][3]=0.f;

#pragma unroll
        for (int kk = 0; kk < 192; kk += 16) {
            unsigned af[2][4];
#pragma unroll
            for (int mt = 0; mt < 2; mt++)
                ldsm4(af[mt], &As[(wm*32 + mt*16 + (g & 1)*8 + r8)*AST + kk + (g >> 1)*8]);
#pragma unroll
            for (int nt16 = 0; nt16 < 2; nt16++) {
                unsigned bf2[4];
                ldsm4(bf2, &Bs[(wn*32 + nt16*16 + (g >> 1)*8 + r8)*AST + kk + (g & 1)*8]);
#pragma unroll
                for (int mt = 0; mt < 2; mt++) {
                    mma16816(acc[mt][nt16*2],     af[mt], bf2);
                    mma16816(acc[mt][nt16*2 + 1], af[mt], bf2 + 2);
                }
            }
        }

        const int cbase = ch*64 + wn*32;
#pragma unroll
        for (int mt = 0; mt < 2; mt++) {
#pragma unroll
            for (int half = 0; half < 2; half++) {
                int gr = row0 + wm*32 + mt*16 + lr + half*8;
                if (EPI == EPI_QKV) {
                    __nv_bfloat16* orow = outH + (size_t)gr*Nfull + cbase;
#pragma unroll
                    for (int nt = 0; nt < 4; nt++) {
                        __nv_bfloat162 pr = __floats2bfloat162_rn(
                            acc[mt][nt][half*2], acc[mt][nt][half*2 + 1]);
                        *(__nv_bfloat162*)(orow + nt*8 + lc) = pr;
                    }
                } else if (EPI == EPI_MLP1) {
                    __nv_bfloat16* orow = outH + (size_t)gr*Nfull + cbase;
#pragma unroll
                    for (int nt = 0; nt < 4; nt++) {
                        float v0 = acc[mt][nt][half*2]     + __ldg(bias + cbase + nt*8 + lc);
                        float v1 = acc[mt][nt][half*2 + 1] + __ldg(bias + cbase + nt*8 + lc + 1);
                        v0 = gelu_tanh(v0);
                        v1 = gelu_tanh(v1);
                        *(__nv_bfloat162*)(orow + nt*8 + lc) = __floats2bfloat162_rn(v0, v1);
                    }
                } else { // EPI_PROJ
                    int bq = gr / TOK_IMG;
                    int rr = (gr / HW) % HW;
                    int cc = gr % HW;
                    int drow = bq * TOK_IMG + ((rr + 3) % HW) * HW + ((cc + 3) % HW);
                    float* orow = outF + (size_t)drow*DIM + cbase;
                    const float* rrow = resid + (size_t)drow*DIM + cbase;
#pragma unroll
                    for (int nt = 0; nt < 4; nt++) {
                        float2 rs = *(const float2*)(rrow + nt*8 + lc);
                        float2 ov;
                        ov.x = acc[mt][nt][half*2]     + __ldg(bias + cbase + nt*8 + lc)     + rs.x;
                        ov.y = acc[mt][nt][half*2 + 1] + __ldg(bias + cbase + nt*8 + lc + 1) + rs.y;
                        *(float2*)(orow + nt*8 + lc) = ov;
                    }
                }
            }
        }
    }
}

// ---------------- K-staged GEMM (MLP2, K=768) ----------------
#define GSTRIDE 72
#define STAGE_A  (256*GSTRIDE)
#define STAGE_B  (64*GSTRIDE)
#define STAGE_EL (STAGE_A + STAGE_B)
#define STAGE_BY (STAGE_EL*2)
#define GEMM_SMEM (2*STAGE_BY)

__global__ void __launch_bounds__(256, 2) gemm_mlp2(
    const __nv_bfloat16* __restrict__ A, const __nv_bfloat16* __restrict__ Bt,
    int K,
    const float* __restrict__ bias, const float* __restrict__ resid,
    float* __restrict__ outF)
{
    extern __shared__ __align__(16) unsigned char smem[];
    const int tid  = threadIdx.x;
    const int warp = tid >> 5;
    const int lane = tid & 31;
    const int wm   = warp >> 1;
    const int wn   = warp & 1;
    const int row0 = blockIdx.y * 256;
    const int col0 = blockIdx.x * 64;
    const int g    = lane >> 3;
    const int r8   = lane & 7;

    float acc[4][4][4];
#pragma unroll
    for (int mt = 0; mt < 4; mt++)
#pragma unroll
        for (int nt = 0; nt < 4; nt++)
            acc[mt][nt][0]=acc[mt][nt][1]=acc[mt][nt][2]=acc[mt][nt][3]=0.f;

    auto loadStage = [&](int kb, int s) {
        __nv_bfloat16* As = (__nv_bfloat16*)(smem + (size_t)s * STAGE_BY);
        __nv_bfloat16* Bs = As + STAGE_A;
#pragma unroll
        for (int l = 0; l < 8; l++) {
            int v = tid + l*256;
            int rr = v >> 3, c = (v & 7) * 8;
            cp16(&As[rr*GSTRIDE + c], A + (size_t)(row0 + rr)*K + kb + c);
        }
#pragma unroll
        for (int l = 0; l < 2; l++) {
            int v = tid + l*256;
            int rn = v >> 3, c = (v & 7) * 8;
            cp16(&Bs[rn*GSTRIDE + c], Bt + (size_t)(col0 + rn)*K + kb + c);
        }
        cp_commit();
    };

    const int T = K >> 6;
    loadStage(0, 0);
    for (int t = 0; t < T; t++) {
        cp_wait<0>();
        __syncthreads();
        if (t + 1 < T) loadStage((t + 1) << 6, (t + 1) & 1);
        __nv_bfloat16* As = (__nv_bfloat16*)(smem + (size_t)(t & 1) * STAGE_BY);
        __nv_bfloat16* Bs = As + STAGE_A;
#pragma unroll
        for (int kk = 0; kk < 64; kk += 16) {
            unsigned af[4][4];
#pragma unroll
            for (int mt = 0; mt < 4; mt++)
                ldsm4(af[mt], &As[(wm*64 + mt*16 + (g & 1)*8 + r8)*GSTRIDE + kk + (g >> 1)*8]);
#pragma unroll
            for (int nt16 = 0; nt16 < 2; nt16++) {
                unsigned bf2[4];
                ldsm4(bf2, &Bs[(wn*32 + nt16*16 + (g >> 1)*8 + r8)*GSTRIDE + kk + (g & 1)*8]);
#pragma unroll
                for (int mt = 0; mt < 4; mt++) {
                    mma16816(acc[mt][nt16*2],     af[mt], bf2);
                    mma16816(acc[mt][nt16*2 + 1], af[mt], bf2 + 2);
                }
            }
        }
    }

    const int lr = lane >> 2;
    const int lc = (lane & 3) * 2;
    const int cbase = col0 + wn*32;

#pragma unroll
    for (int mt = 0; mt < 4; mt++) {
#pragma unroll
        for (int half = 0; half < 2; half++) {
            int gr = row0 + wm*64 + mt*16 + lr + half*8;
            float* orow = outF + (size_t)gr*DIM + cbase;
            const float* rrow = resid + (size_t)gr*DIM + cbase;
#pragma unroll
            for (int nt = 0; nt < 4; nt++) {
                float2 rs = *(const float2*)(rrow + nt*8 + lc);
                float2 ov;
                ov.x = acc[mt][nt][half*2]     + __ldg(bias + cbase + nt*8 + lc)     + rs.x;
                ov.y = acc[mt][nt][half*2 + 1] + __ldg(bias + cbase + nt*8 + lc + 1) + rs.y;
                *(float2*)(orow + nt*8 + lc) = ov;
            }
        }
    }
}

// ---------------- window attention (cp.async loads, register softmax) ----------------
__global__ void __launch_bounds__(128) attn_kernel(
    const __nv_bfloat16* __restrict__ qkv, const float* __restrict__ bias2,
    __nv_bfloat16* __restrict__ outA)
{
    __shared__ __align__(16) __nv_bfloat16 sQ[64*40];
    __shared__ __align__(16) __nv_bfloat16 sK[64*40];
    __shared__ __align__(16) __nv_bfloat16 sV[64*40];

    int tid = threadIdx.x, w = tid >> 5, lane = tid & 31;
    int h = blockIdx.x, win = blockIdx.y, b = blockIdx.z;
    int wi = win >> 4, wj = win & 15;
    bool mul = (wi == NWIN-1), mlr = (wj == NWIN-1);
    int tokbase = (b*HW + wi*WS)*HW + wj*WS;

    // zero V pad rows 49..63 (regular STS; disjoint from cp.async region)
    uint4 z4 = make_uint4(0,0,0,0);
    for (int e = tid; e < 60; e += 128) {
        int rr = 49 + (e >> 2), ch = e & 3;
        *(uint4*)&sV[rr*40 + ch*8] = z4;
    }
    // async gather of Q/K/V rows
    for (int e = tid; e < 196; e += 128) {
        int i = e >> 2, ch = e & 3;
        int t = tokbase + (i/WS)*HW + (i%WS);
        const __nv_bfloat16* p = qkv + (size_t)t*576 + h*HD + ch*8;
        cp16(&sQ[i*40 + ch*8], p);
        cp16(&sK[i*40 + ch*8], p + 192);
        cp16(&sV[i*40 + ch*8], p + 384);
    }
    cp_commit();
    cp_wait<0>();
    __syncthreads();

    int g = lane >> 3, r = lane & 7;

    unsigned qa[2][4];
#pragma unroll
    for (int kt = 0; kt < 2; kt++)
        ldsm4(qa[kt], &sQ[(w*16 + (g & 1)*8 + r)*40 + kt*16 + (g >> 1)*8]);

    float acc[8][4];
#pragma unroll
    for (int t = 0; t < 8; t++) { acc[t][0]=acc[t][1]=acc[t][2]=acc[t][3]=0.f; }
#pragma unroll
    for (int nt = 0; nt < 4; nt++) {
#pragma unroll
        for (int kt = 0; kt < 2; kt++) {
            unsigned bk[4];
            ldsm4(bk, &sK[(nt*16 + (g >> 1)*8 + r)*40 + kt*16 + (g & 1)*8]);
            mma16816(acc[nt*2],     qa[kt], bk);
            mma16816(acc[nt*2 + 1], qa[kt], bk + 2);
        }
    }

    const float SC = 0.17677669529663689f;
    int q2 = (lane & 3)*2;
    bool jb[16], j7[16], jp[16];
#pragma unroll
    for (int e = 0; e < 16; e++) {
        int j = (e >> 1)*8 + q2 + (e & 1);
        jb[e] = (j >= 28); j7[e] = ((j % 7) >= 4); jp[e] = (j >= WS2);
    }
#pragma unroll
    for (int sel = 0; sel < 2; sel++) {
        int i = w*16 + (lane >> 2) + sel*8;
        bool ib = (i >= 28), i7 = ((i % 7) >= 4);
        float v[16];
        float mx = -1e30f;
#pragma unroll
        for (int t = 0; t < 8; t++) {
            float2 bb = *(const float2*)&bias2[i*64 + t*8 + q2];
            float v0 = fmaf(acc[t][sel*2],     SC, bb.x);
            float v1 = fmaf(acc[t][sel*2 + 1], SC, bb.y);
            if (mul && (ib != jb[2*t]))     v0 -= 1e9f;
            if (mlr && (i7 != j7[2*t]))     v0 -= 1e9f;
            if (mul && (ib != jb[2*t + 1])) v1 -= 1e9f;
            if (mlr && (i7 != j7[2*t + 1])) v1 -= 1e9f;
            if (jp[2*t])     v0 = -1e9f;
            if (jp[2*t + 1]) v1 = -1e9f;
            v[2*t] = v0; v[2*t + 1] = v1;
            mx = fmaxf(mx, fmaxf(v0, v1));
        }
        mx = fmaxf(mx, __shfl_xor_sync(0xffffffffu, mx, 1));
        mx = fmaxf(mx, __shfl_xor_sync(0xffffffffu, mx, 2));
        float sum = 0.f;
#pragma unroll
        for (int e = 0; e < 16; e++) { float ev = __expf(v[e] - mx); v[e] = ev; sum += ev; }
        sum += __shfl_xor_sync(0xffffffffu, sum, 1);
        sum += __shfl_xor_sync(0xffffffffu, sum, 2);
        float inv = 1.f / sum;
#pragma unroll
        for (int t = 0; t < 8; t++) {
            acc[t][sel*2]     = v[2*t] * inv;
            acc[t][sel*2 + 1] = v[2*t + 1] * inv;
        }
    }

    float o[4][4];
#pragma unroll
    for (int t = 0; t < 4; t++) { o[t][0]=o[t][1]=o[t][2]=o[t][3]=0.f; }
#pragma unroll
    for (int kt = 0; kt < 4; kt++) {
        unsigned pa[4];
        __nv_bfloat162 t0 = __floats2bfloat162_rn(acc[2*kt][0],     acc[2*kt][1]);
        __nv_bfloat162 t1 = __floats2bfloat162_rn(acc[2*kt][2],     acc[2*kt][3]);
        __nv_bfloat162 t2 = __floats2bfloat162_rn(acc[2*kt + 1][0], acc[2*kt + 1][1]);
        __nv_bfloat162 t3 = __floats2bfloat162_rn(acc[2*kt + 1][2], acc[2*kt + 1][3]);
        pa[0] = *(unsigned*)&t0; pa[1] = *(unsigned*)&t1;
        pa[2] = *(unsigned*)&t2; pa[3] = *(unsigned*)&t3;
        unsigned bv[4];
        ldsm4t(bv, &sV[(kt*16 + (g & 1)*8 + r)*40 + (g >> 1)*8]);
        mma16816(o[0], pa, bv);
        mma16816(o[1], pa, bv + 2);
        ldsm4t(bv, &sV[(kt*16 + (g & 1)*8 + r)*40 + 16 + (g >> 1)*8]);
        mma16816(o[2], pa, bv);
        mma16816(o[3], pa, bv + 2);
    }

#pragma unroll
    for (int sel = 0; sel < 2; sel++) {
        int i = w*16 + (lane >> 2) + sel*8;
        if (i < WS2) {
            int tok = tokbase + (i/WS)*HW + (i%WS);
            __nv_bfloat16* po = outA + (size_t)tok*INNER + h*HD + q2;
#pragma unroll
            for (int dt = 0; dt < 4; dt++) {
                __nv_bfloat162 pr = __floats2bfloat162_rn(o[dt][sel*2], o[dt][sel*2 + 1]);
                *(__nv_bfloat162*)(po + dt*8) = pr;
            }
        }
    }
}

// ---------------- launch ----------------
extern "C" void kernel_launch(void* const* d_in, const int* in_sizes, int n_in,
                              void* d_out, int out_size)
{
    const float* x      = (const float*)d_in[0];
    const float* w_qkv  = (const float*)d_in[1];
    const float* w_out  = (const float*)d_in[2];
    const float* b_out  = (const float*)d_in[3];
    const float* pos    = (const float*)d_in[4];
    const float* ln1_g  = (const float*)d_in[5];
    const float* ln1_b  = (const float*)d_in[6];
    const float* ln2_g  = (const float*)d_in[7];
    const float* ln2_b  = (const float*)d_in[8];
    const float* w1     = (const float*)d_in[9];
    const float* b1     = (const float*)d_in[10];
    const float* w2     = (const float*)d_in[11];
    const float* b2     = (const float*)d_in[12];
    float* out = (float*)d_out;

    void *p_qkv, *p_attn, *p_x2, *p_mlp;
    void *p_wqkvT, *p_woutT, *p_w1T, *p_w2T, *p_bias;
    cudaGetSymbolAddress(&p_qkv,  g_qkv);
    cudaGetSymbolAddress(&p_attn, g_attn);
    cudaGetSymbolAddress(&p_x2,   g_x2);
    cudaGetSymbolAddress(&p_mlp,  g_mlp);
    cudaGetSymbolAddress(&p_wqkvT, g_wqkvT);
    cudaGetSymbolAddress(&p_woutT, g_woutT);
    cudaGetSymbolAddress(&p_w1T,   g_w1T);
    cudaGetSymbolAddress(&p_w2T,   g_w2T);
    cudaGetSymbolAddress(&p_bias,  g_bias2);

    static bool attr_done = false;
    if (!attr_done) {
        cudaFuncSetAttribute((const void*)gemm_ares<EPI_QKV, 9, 1, 1>,
                             cudaFuncAttributeMaxDynamicSharedMemorySize, ARES_SMEM);
        cudaFuncSetAttribute((const void*)gemm_ares<EPI_PROJ, 3, 0, 0>,
                             cudaFuncAttributeMaxDynamicSharedMemorySize, ARES_SMEM);
        cudaFuncSetAttribute((const void*)gemm_ares<EPI_MLP1, 12, 1, 0>,
                             cudaFuncAttributeMaxDynamicSharedMemorySize, ARES_SMEM);
        cudaFuncSetAttribute((const void*)gemm_mlp2,
                             cudaFuncAttributeMaxDynamicSharedMemorySize, GEMM_SMEM);
        attr_done = true;
    }

    // 432 transpose tiles + 16 bias blocks
    convert_kernel<<<448, 256>>>(
        w_qkv, w_out, w1, w2, pos,
        (__nv_bfloat16*)p_wqkvT, (__nv_bfloat16*)p_woutT,
        (__nv_bfloat16*)p_w1T, (__nv_bfloat16*)p_w2T, (float*)p_bias);

    // QKV with fused shifted LN1 on A
    gemm_ares<EPI_QKV, 9, 1, 1><<<TOKENS/128, 256, ARES_SMEM>>>(
        nullptr, x, ln1_g, ln1_b,
        (const __nv_bfloat16*)p_wqkvT, 576,
        nullptr, nullptr, nullptr, (__nv_bfloat16*)p_qkv);

    attn_kernel<<<dim3(HEADS, NWIN*NWIN, BATCH), 128>>>(
        (const __nv_bfloat16*)p_qkv, (const float*)p_bias, (__nv_bfloat16*)p_attn);

    // PROJ + back-shift + residual -> x2
    gemm_ares<EPI_PROJ, 3, 0, 0><<<TOKENS/128, 256, ARES_SMEM>>>(
        (const __nv_bfloat16*)p_attn, nullptr, nullptr, nullptr,
        (const __nv_bfloat16*)p_woutT, DIM,
        b_out, x, (float*)p_x2, nullptr);

    // MLP1 with fused LN2 on A + tanh-GELU
    gemm_ares<EPI_MLP1, 12, 1, 0><<<TOKENS/128, 256, ARES_SMEM>>>(
        nullptr, (const float*)p_x2, ln2_g, ln2_b,
        (const __nv_bfloat16*)p_w1T, MLPD,
        b1, nullptr, nullptr, (__nv_bfloat16*)p_mlp);

    // MLP2 + residual -> out
    gemm_mlp2<<<dim3(DIM/64, TOKENS/256), 256, GEMM_SMEM>>>(
        (const __nv_bfloat16*)p_mlp, (const __nv_bfloat16*)p_w2T, MLPD,
        b2, (const float*)p_x2, out);
}

// round 16
// speedup vs baseline: 1.1205x; 1.0083x over previous
#include <cuda_runtime.h>
#include <cuda_bf16.h>

// ---------------- problem constants ----------------
#define BATCH   8
#define HW      112
#define DIM     192
#define HEADS   6
#define HD      32
#define INNER   192
#define MLPD    768
#define WS      7
#define WS2     49
#define NWIN    16
#define TOKENS  (BATCH*HW*HW)        // 100352
#define TOK_IMG (HW*HW)              // 12544

// ---------------- scratch ----------------
__device__ __nv_bfloat16 g_qkv [(size_t)TOKENS*576];
__device__ __nv_bfloat16 g_attn[(size_t)TOKENS*INNER];
__device__ float         g_x2  [(size_t)TOKENS*DIM];
__device__ __nv_bfloat16 g_wqkvT[576*DIM];     // [N][K]
__device__ __nv_bfloat16 g_woutT[DIM*INNER];
__device__ __nv_bfloat16 g_w1T  [MLPD*DIM];
__device__ __nv_bfloat16 g_w2T  [DIM*MLPD];
__device__ float         g_bias2[64*64];

// ---------------- helpers ----------------
__device__ __forceinline__ void cp16(void* s, const void* g) {
    unsigned sa = (unsigned)__cvta_generic_to_shared(s);
    asm volatile("cp.async.cg.shared.global [%0], [%1], 16;\n" :: "r"(sa), "l"(g));
}
__device__ __forceinline__ void cp_commit() { asm volatile("cp.async.commit_group;\n"); }
template<int N> __device__ __forceinline__ void cp_wait() {
    asm volatile("cp.async.wait_group %0;\n" :: "n"(N));
}
__device__ __forceinline__ void ldsm4(unsigned* r, const void* p) {
    unsigned a = (unsigned)__cvta_generic_to_shared(p);
    asm volatile("ldmatrix.sync.aligned.m8n8.x4.shared.b16 {%0,%1,%2,%3}, [%4];\n"
        : "=r"(r[0]),"=r"(r[1]),"=r"(r[2]),"=r"(r[3]) : "r"(a));
}
__device__ __forceinline__ void ldsm4t(unsigned* r, const void* p) {
    unsigned a = (unsigned)__cvta_generic_to_shared(p);
    asm volatile("ldmatrix.sync.aligned.m8n8.x4.trans.shared.b16 {%0,%1,%2,%3}, [%4];\n"
        : "=r"(r[0]),"=r"(r[1]),"=r"(r[2]),"=r"(r[3]) : "r"(a));
}
__device__ __forceinline__ void mma16816(float* d, const unsigned* a, const unsigned* b) {
    asm volatile("mma.sync.aligned.m16n8k16.row.col.f32.bf16.bf16.f32 "
        "{%0,%1,%2,%3}, {%4,%5,%6,%7}, {%8,%9}, {%0,%1,%2,%3};\n"
        : "+f"(d[0]),"+f"(d[1]),"+f"(d[2]),"+f"(d[3])
        : "r"(a[0]),"r"(a[1]),"r"(a[2]),"r"(a[3]), "r"(b[0]),"r"(b[1]));
}
__device__ __forceinline__ float gelu_tanh(float x) {
    float t = __tanhf(0.7978845608028654f * fmaf(0.044715f * x * x, x, x));
    return 0.5f * x * (1.f + t);
}

// ---------------- coalesced transpose-convert + rel-bias ----------------
__global__ void __launch_bounds__(256) convert_kernel(
    const float* __restrict__ wqkv, const float* __restrict__ wout,
    const float* __restrict__ w1, const float* __restrict__ w2,
    const float* __restrict__ pos,
    __nv_bfloat16* __restrict__ o_qkvT, __nv_bfloat16* __restrict__ o_outT,
    __nv_bfloat16* __restrict__ o_w1T, __nv_bfloat16* __restrict__ o_w2T,
    float* __restrict__ bias2)
{
    __shared__ float tile[32][33];
    int bid = blockIdx.x;
    const float* src; __nv_bfloat16* dst; int K, N, tid0;
    if (bid < 108)      { src = wqkv; dst = o_qkvT; K = 192; N = 576; tid0 = bid; }
    else if (bid < 144) { src = wout; dst = o_outT; K = 192; N = 192; tid0 = bid - 108; }
    else if (bid < 288) { src = w1;   dst = o_w1T;  K = 192; N = 768; tid0 = bid - 144; }
    else if (bid < 432) { src = w2;   dst = o_w2T;  K = 768; N = 192; tid0 = bid - 288; }
    else {
        int i = (bid - 432) * 256 + threadIdx.x;
        int r = i >> 6, c = i & 63;
        float v = 0.f;
        if (r < WS2 && c < WS2) {
            int ri = r / WS, ci = r % WS, rj = c / WS, cj = c % WS;
            v = pos[(ri - rj + WS - 1) * (2*WS - 1) + (ci - cj + WS - 1)];
        }
        bias2[i] = v;
        return;
    }
    int ntiles_n = N >> 5;
    int n0 = (tid0 % ntiles_n) * 32;
    int k0 = (tid0 / ntiles_n) * 32;
    int tc = threadIdx.x & 31, tr = threadIdx.x >> 5;
#pragma unroll
    for (int rr = 0; rr < 4; rr++) {
        int r = tr + rr*8;
        tile[r][tc] = src[(size_t)(k0 + r)*N + n0 + tc];
    }
    __syncthreads();
#pragma unroll
    for (int rr = 0; rr < 4; rr++) {
        int r = tr + rr*8;
        dst[(size_t)(n0 + r)*K + k0 + tc] = __float2bfloat16(tile[tc][r]);
    }
}

enum { EPI_QKV = 0, EPI_PROJ = 1 };

// ---------------- A-resident GEMM (K=192), 2 CTAs/SM, optional fused LN on A ----------------
#define AST 200
#define ARES_A_BY  (128*AST*2)
#define ARES_B_BY  (64*AST*2)
#define ARES_SMEM  (ARES_A_BY + 2*ARES_B_BY)

template<int EPI, int NC, int LNA, int LNSHIFT>
__global__ void __launch_bounds__(256, 2) gemm_ares(
    const __nv_bfloat16* __restrict__ A, const float* __restrict__ lnSrc,
    const float* __restrict__ lng, const float* __restrict__ lnb,
    const __nv_bfloat16* __restrict__ Bt, int Nfull,
    const float* __restrict__ bias, const float* __restrict__ resid,
    float* __restrict__ outF, __nv_bfloat16* __restrict__ outH)
{
    extern __shared__ __align__(16) unsigned char smem[];
    __nv_bfloat16* As = (__nv_bfloat16*)smem;
    const int tid  = threadIdx.x;
    const int warp = tid >> 5;
    const int lane = tid & 31;
    const int wm   = warp >> 1;
    const int wn   = warp & 1;
    const int row0 = blockIdx.x * 128;
    const int g    = lane >> 3;
    const int r8   = lane & 7;

    {
        __nv_bfloat16* Bs = (__nv_bfloat16*)(smem + ARES_A_BY);
#pragma unroll
        for (int l = 0; l < 6; l++) {
            int cid = l*256 + tid;
            int rn = cid / 24, c = cid % 24;
            cp16(&Bs[rn*AST + c*8], Bt + (size_t)rn*192 + c*8);
        }
    }

    if (LNA) {
#pragma unroll 4
        for (int rr = 0; rr < 16; rr++) {
            int rl = warp*16 + rr;
            int gr = row0 + rl;
            size_t src;
            if (LNSHIFT) {
                int bq = gr / TOK_IMG;
                int r2 = (gr / HW) % HW;
                int c2 = gr % HW;
                src = (size_t)(bq * TOK_IMG + ((r2 + 3) % HW) * HW + ((c2 + 3) % HW)) * DIM;
            } else {
                src = (size_t)gr * DIM;
            }
            float v[6];
            float s = 0.f, q = 0.f;
#pragma unroll
            for (int k = 0; k < 6; k++) {
                v[k] = __ldg(lnSrc + src + lane + 32*k);
                s += v[k]; q += v[k]*v[k];
            }
#pragma unroll
            for (int o = 16; o > 0; o >>= 1) {
                s += __shfl_xor_sync(0xffffffffu, s, o);
                q += __shfl_xor_sync(0xffffffffu, q, o);
            }
            float mean = s * (1.f/DIM);
            float rstd = rsqrtf(q * (1.f/DIM) - mean*mean + 1e-5f);
#pragma unroll
            for (int k = 0; k < 6; k++) {
                int c = lane + 32*k;
                As[rl*AST + c] = __float2bfloat16((v[k] - mean) * rstd * __ldg(lng + c) + __ldg(lnb + c));
            }
        }
    } else {
#pragma unroll
        for (int l = 0; l < 12; l++) {
            int cid = l*256 + tid;
            int r = cid / 24, c = cid % 24;
            cp16(&As[r*AST + c*8], A + (size_t)(row0 + r)*192 + c*8);
        }
    }
    cp_commit();

    const int lr = lane >> 2;
    const int lc = (lane & 3) * 2;

    for (int ch = 0; ch < NC; ch++) {
        cp_wait<0>();
        __syncthreads();
        if (ch + 1 < NC) {
            __nv_bfloat16* Bn = (__nv_bfloat16*)(smem + ARES_A_BY + ((ch + 1) & 1) * ARES_B_BY);
            const __nv_bfloat16* src = Bt + (size_t)(ch + 1)*64*192;
#pragma unroll
            for (int l = 0; l < 6; l++) {
                int cid = l*256 + tid;
                int rn = cid / 24, c = cid % 24;
                cp16(&Bn[rn*AST + c*8], src + (size_t)rn*192 + c*8);
            }
            cp_commit();
        }
        __nv_bfloat16* Bs = (__nv_bfloat16*)(smem + ARES_A_BY + (ch & 1) * ARES_B_BY);

        float acc[2][4][4];
#pragma unroll
        for (int mt = 0; mt < 2; mt++)
#pragma unroll
            for (int nt = 0; nt < 4; nt++)
                acc[mt][nt][0]=acc[mt][nt][1]=acc[mt][nt][2]=acc[mt][nt][3]=0.f;

#pragma unroll
        for (int kk = 0; kk < 192; kk += 16) {
            unsigned af[2][4];
#pragma unroll
            for (int mt = 0; mt < 2; mt++)
                ldsm4(af[mt], &As[(wm*32 + mt*16 + (g & 1)*8 + r8)*AST + kk + (g >> 1)*8]);
#pragma unroll
            for (int nt16 = 0; nt16 < 2; nt16++) {
                unsigned bf2[4];
                ldsm4(bf2, &Bs[(wn*32 + nt16*16 + (g >> 1)*8 + r8)*AST + kk + (g & 1)*8]);
#pragma unroll
                for (int mt = 0; mt < 2; mt++) {
                    mma16816(acc[mt][nt16*2],     af[mt], bf2);
                    mma16816(acc[mt][nt16*2 + 1], af[mt], bf2 + 2);
                }
            }
        }

        const int cbase = ch*64 + wn*32;
#pragma unroll
        for (int mt = 0; mt < 2; mt++) {
#pragma unroll
            for (int half = 0; half < 2; half++) {
                int gr = row0 + wm*32 + mt*16 + lr + half*8;
                if (EPI == EPI_QKV) {
                    __nv_bfloat16* orow = outH + (size_t)gr*Nfull + cbase;
#pragma unroll
                    for (int nt = 0; nt < 4; nt++) {
                        __nv_bfloat162 pr = __floats2bfloat162_rn(
                            acc[mt][nt][half*2], acc[mt][nt][half*2 + 1]);
                        *(__nv_bfloat162*)(orow + nt*8 + lc) = pr;
                    }
                } else { // EPI_PROJ
                    int bq = gr / TOK_IMG;
                    int rr = (gr / HW) % HW;
                    int cc = gr % HW;
                    int drow = bq * TOK_IMG + ((rr + 3) % HW) * HW + ((cc + 3) % HW);
                    float* orow = outF + (size_t)drow*DIM + cbase;
                    const float* rrow = resid + (size_t)drow*DIM + cbase;
#pragma unroll
                    for (int nt = 0; nt < 4; nt++) {
                        float2 rs = *(const float2*)(rrow + nt*8 + lc);
                        float2 ov;
                        ov.x = acc[mt][nt][half*2]     + __ldg(bias + cbase + nt*8 + lc)     + rs.x;
                        ov.y = acc[mt][nt][half*2 + 1] + __ldg(bias + cbase + nt*8 + lc + 1) + rs.y;
                        *(float2*)(orow + nt*8 + lc) = ov;
                    }
                }
            }
        }
    }
}

// ---------------- fused MLP: out = gelu(LN(x2)@w1+b1)@w2 + b2 + x2 ----------------
// CTA = 64 rows, 256 thr / 8 warps, 2 CTAs/SM. Hidden dim processed in 12 chunks of 64;
// gelu output never leaves smem; out accumulates in registers (64x192 / 256 thr = 48 regs).
#define F_AS_BY   (64*AST*2)          // 25600
#define F_BUFA_BY (64*AST*2)          // 25600 (w1 chunk [64][AST])
#define F_BUFB_BY (192*72*2)          // 27648 (w2 slice [192][72])
#define F_HS_BY   (64*72*2)           // 9216
#define F_OFF_BUFA (F_AS_BY)
#define F_OFF_BUFB (F_AS_BY + F_BUFA_BY)
#define F_OFF_HS   (F_AS_BY + F_BUFA_BY + F_BUFB_BY)
#define FUSED_SMEM (F_AS_BY + F_BUFA_BY + F_BUFB_BY + F_HS_BY)   // 88064

__global__ void __launch_bounds__(256, 2) gemm_mlpfused(
    const float* __restrict__ x2,
    const float* __restrict__ lng, const float* __restrict__ lnb,
    const __nv_bfloat16* __restrict__ w1T, const float* __restrict__ b1,
    const __nv_bfloat16* __restrict__ w2T, const float* __restrict__ b2,
    float* __restrict__ out)
{
    extern __shared__ __align__(16) unsigned char smem[];
    __nv_bfloat16* As   = (__nv_bfloat16*)smem;
    __nv_bfloat16* BufA = (__nv_bfloat16*)(smem + F_OFF_BUFA);
    __nv_bfloat16* BufB = (__nv_bfloat16*)(smem + F_OFF_BUFB);
    __nv_bfloat16* Hs   = (__nv_bfloat16*)(smem + F_OFF_HS);

    const int tid  = threadIdx.x;
    const int warp = tid >> 5;
    const int lane = tid & 31;
    const int wm   = warp >> 1;       // 0..3 : 16-row strip
    const int wn   = warp & 1;        // 0..1
    const int row0 = blockIdx.x * 64;
    const int g    = lane >> 3;
    const int r8   = lane & 7;
    const int lr   = lane >> 2;
    const int lc   = (lane & 3) * 2;

    // preload w1 chunk 0 (64 rows x 192) — overlaps LN prologue
#pragma unroll
    for (int l = 0; l < 6; l++) {
        int cid = l*256 + tid;
        int rn = cid / 24, c = cid % 24;
        cp16(&BufA[rn*AST + c*8], w1T + (size_t)rn*192 + c*8);
    }
    cp_commit();

    // LN2 prologue: 8 warps x 8 rows
#pragma unroll 4
    for (int rr = 0; rr < 8; rr++) {
        int rl = warp*8 + rr;
        size_t src = (size_t)(row0 + rl) * DIM;
        float v[6];
        float s = 0.f, q = 0.f;
#pragma unroll
        for (int k = 0; k < 6; k++) {
            v[k] = __ldg(x2 + src + lane + 32*k);
            s += v[k]; q += v[k]*v[k];
        }
#pragma unroll
        for (int o = 16; o > 0; o >>= 1) {
            s += __shfl_xor_sync(0xffffffffu, s, o);
            q += __shfl_xor_sync(0xffffffffu, q, o);
        }
        float mean = s * (1.f/DIM);
        float rstd = rsqrtf(q * (1.f/DIM) - mean*mean + 1e-5f);
#pragma unroll
        for (int k = 0; k < 6; k++) {
            int c = lane + 32*k;
            As[rl*AST + c] = __float2bfloat16((v[k] - mean) * rstd * __ldg(lng + c) + __ldg(lnb + c));
        }
    }

    float oacc[12][4];
#pragma unroll
    for (int nt = 0; nt < 12; nt++)
        oacc[nt][0]=oacc[nt][1]=oacc[nt][2]=oacc[nt][3]=0.f;

    for (int ch = 0; ch < 12; ch++) {
        cp_wait<0>();          // w1 chunk ch ready; prev out-gemm (BufB reads) done pre-sync
        __syncthreads();

        // prefetch w2 slice ch : 192 rows x 64 cols
#pragma unroll
        for (int l = 0; l < 6; l++) {
            int cid = l*256 + tid;
            int rn = cid >> 3, c = cid & 7;
            cp16(&BufB[rn*72 + c*8], w2T + (size_t)rn*768 + ch*64 + c*8);
        }
        cp_commit();

        // h = As(64x192) @ BufA(64 n-rows x 192 k) -> 64x64
        float hacc[4][4];
#pragma unroll
        for (int nt = 0; nt < 4; nt++)
            hacc[nt][0]=hacc[nt][1]=hacc[nt][2]=hacc[nt][3]=0.f;
#pragma unroll
        for (int kk = 0; kk < 192; kk += 16) {
            unsigned af[4];
            ldsm4(af, &As[(wm*16 + (g & 1)*8 + r8)*AST + kk + (g >> 1)*8]);
#pragma unroll
            for (int nt16 = 0; nt16 < 2; nt16++) {
                unsigned bf2[4];
                ldsm4(bf2, &BufA[(wn*32 + nt16*16 + (g >> 1)*8 + r8)*AST + kk + (g & 1)*8]);
                mma16816(hacc[nt16*2],     af, bf2);
                mma16816(hacc[nt16*2 + 1], af, bf2 + 2);
            }
        }
        // gelu(+b1) -> Hs bf16
#pragma unroll
        for (int half = 0; half < 2; half++) {
            int row = wm*16 + lr + half*8;
#pragma unroll
            for (int nt = 0; nt < 4; nt++) {
                int col = wn*32 + nt*8 + lc;
                float v0 = hacc[nt][half*2]     + __ldg(b1 + ch*64 + col);
                float v1 = hacc[nt][half*2 + 1] + __ldg(b1 + ch*64 + col + 1);
                v0 = gelu_tanh(v0);
                v1 = gelu_tanh(v1);
                *(__nv_bfloat162*)&Hs[row*72 + col] = __floats2bfloat162_rn(v0, v1);
            }
        }
        cp_wait<0>();          // w2 slice ready
        __syncthreads();       // Hs fully written, BufA free

        if (ch + 1 < 12) {     // prefetch next w1 chunk into BufA
            const __nv_bfloat16* src = w1T + (size_t)(ch + 1)*64*192;
#pragma unroll
            for (int l = 0; l < 6; l++) {
                int cid = l*256 + tid;
                int rn = cid / 24, c = cid % 24;
                cp16(&BufA[rn*AST + c*8], src + (size_t)rn*192 + c*8);
            }
            cp_commit();
        }

        // out += Hs(64x64) @ BufB(192 n-rows x 64 k)
#pragma unroll
        for (int kk = 0; kk < 64; kk += 16) {
            unsigned af[4];
            ldsm4(af, &Hs[(wm*16 + (g & 1)*8 + r8)*72 + kk + (g >> 1)*8]);
#pragma unroll
            for (int nt16 = 0; nt16 < 6; nt16++) {
                unsigned bf2[4];
                ldsm4(bf2, &BufB[(wn*96 + nt16*16 + (g >> 1)*8 + r8)*72 + kk + (g & 1)*8]);
                mma16816(oacc[nt16*2],     af, bf2);
                mma16816(oacc[nt16*2 + 1], af, bf2 + 2);
            }
        }
    }

    // epilogue: + b2 + x2 residual -> out
#pragma unroll
    for (int half = 0; half < 2; half++) {
        int gr = row0 + wm*16 + lr + half*8;
        float* orow = out + (size_t)gr*DIM + wn*96;
        const float* rrow = x2 + (size_t)gr*DIM + wn*96;
#pragma unroll
        for (int nt = 0; nt < 12; nt++) {
            float2 rs = *(const float2*)(rrow + nt*8 + lc);
            float2 ov;
            ov.x = oacc[nt][half*2]     + __ldg(b2 + wn*96 + nt*8 + lc)     + rs.x;
            ov.y = oacc[nt][half*2 + 1] + __ldg(b2 + wn*96 + nt*8 + lc + 1) + rs.y;
            *(float2*)(orow + nt*8 + lc) = ov;
        }
    }
}

// ---------------- window attention (cp.async loads, register softmax) ----------------
__global__ void __launch_bounds__(128) attn_kernel(
    const __nv_bfloat16* __restrict__ qkv, const float* __restrict__ bias2,
    __nv_bfloat16* __restrict__ outA)
{
    __shared__ __align__(16) __nv_bfloat16 sQ[64*40];
    __shared__ __align__(16) __nv_bfloat16 sK[64*40];
    __shared__ __align__(16) __nv_bfloat16 sV[64*40];

    int tid = threadIdx.x, w = tid >> 5, lane = tid & 31;
    int h = blockIdx.x, win = blockIdx.y, b = blockIdx.z;
    int wi = win >> 4, wj = win & 15;
    bool mul = (wi == NWIN-1), mlr = (wj == NWIN-1);
    int tokbase = (b*HW + wi*WS)*HW + wj*WS;

    uint4 z4 = make_uint4(0,0,0,0);
    for (int e = tid; e < 60; e += 128) {
        int rr = 49 + (e >> 2), ch = e & 3;
        *(uint4*)&sV[rr*40 + ch*8] = z4;
    }
    for (int e = tid; e < 196; e += 128) {
        int i = e >> 2, ch = e & 3;
        int t = tokbase + (i/WS)*HW + (i%WS);
        const __nv_bfloat16* p = qkv + (size_t)t*576 + h*HD + ch*8;
        cp16(&sQ[i*40 + ch*8], p);
        cp16(&sK[i*40 + ch*8], p + 192);
        cp16(&sV[i*40 + ch*8], p + 384);
    }
    cp_commit();
    cp_wait<0>();
    __syncthreads();

    int g = lane >> 3, r = lane & 7;

    unsigned qa[2][4];
#pragma unroll
    for (int kt = 0; kt < 2; kt++)
        ldsm4(qa[kt], &sQ[(w*16 + (g & 1)*8 + r)*40 + kt*16 + (g >> 1)*8]);

    float acc[8][4];
#pragma unroll
    for (int t = 0; t < 8; t++) { acc[t][0]=acc[t][1]=acc[t][2]=acc[t][3]=0.f; }
#pragma unroll
    for (int nt = 0; nt < 4; nt++) {
#pragma unroll
        for (int kt = 0; kt < 2; kt++) {
            unsigned bk[4];
            ldsm4(bk, &sK[(nt*16 + (g >> 1)*8 + r)*40 + kt*16 + (g & 1)*8]);
            mma16816(acc[nt*2],     qa[kt], bk);
            mma16816(acc[nt*2 + 1], qa[kt], bk + 2);
        }
    }

    const float SC = 0.17677669529663689f;
    int q2 = (lane & 3)*2;
    bool jb[16], j7[16], jp[16];
#pragma unroll
    for (int e = 0; e < 16; e++) {
        int j = (e >> 1)*8 + q2 + (e & 1);
        jb[e] = (j >= 28); j7[e] = ((j % 7) >= 4); jp[e] = (j >= WS2);
    }
#pragma unroll
    for (int sel = 0; sel < 2; sel++) {
        int i = w*16 + (lane >> 2) + sel*8;
        bool ib = (i >= 28), i7 = ((i % 7) >= 4);
        float v[16];
        float mx = -1e30f;
#pragma unroll
        for (int t = 0; t < 8; t++) {
            float2 bb = *(const float2*)&bias2[i*64 + t*8 + q2];
            float v0 = fmaf(acc[t][sel*2],     SC, bb.x);
            float v1 = fmaf(acc[t][sel*2 + 1], SC, bb.y);
            if (mul && (ib != jb[2*t]))     v0 -= 1e9f;
            if (mlr && (i7 != j7[2*t]))     v0 -= 1e9f;
            if (mul && (ib != jb[2*t + 1])) v1 -= 1e9f;
            if (mlr && (i7 != j7[2*t + 1])) v1 -= 1e9f;
            if (jp[2*t])     v0 = -1e9f;
            if (jp[2*t + 1]) v1 = -1e9f;
            v[2*t] = v0; v[2*t + 1] = v1;
            mx = fmaxf(mx, fmaxf(v0, v1));
        }
        mx = fmaxf(mx, __shfl_xor_sync(0xffffffffu, mx, 1));
        mx = fmaxf(mx, __shfl_xor_sync(0xffffffffu, mx, 2));
        float sum = 0.f;
#pragma unroll
        for (int e = 0; e < 16; e++) { float ev = __expf(v[e] - mx); v[e] = ev; sum += ev; }
        sum += __shfl_xor_sync(0xffffffffu, sum, 1);
        sum += __shfl_xor_sync(0xffffffffu, sum, 2);
        float inv = 1.f / sum;
#pragma unroll
        for (int t = 0; t < 8; t++) {
            acc[t][sel*2]     = v[2*t] * inv;
            acc[t][sel*2 + 1] = v[2*t + 1] * inv;
        }
    }

    float o[4][4];
#pragma unroll
    for (int t = 0; t < 4; t++) { o[t][0]=o[t][1]=o[t][2]=o[t][3]=0.f; }
#pragma unroll
    for (int kt = 0; kt < 4; kt++) {
        unsigned pa[4];
        __nv_bfloat162 t0 = __floats2bfloat162_rn(acc[2*kt][0],     acc[2*kt][1]);
        __nv_bfloat162 t1 = __floats2bfloat162_rn(acc[2*kt][2],     acc[2*kt][3]);
        __nv_bfloat162 t2 = __floats2bfloat162_rn(acc[2*kt + 1][0], acc[2*kt + 1][1]);
        __nv_bfloat162 t3 = __floats2bfloat162_rn(acc[2*kt + 1][2], acc[2*kt + 1][3]);
        pa[0] = *(unsigned*)&t0; pa[1] = *(unsigned*)&t1;
        pa[2] = *(unsigned*)&t2; pa[3] = *(unsigned*)&t3;
        unsigned bv[4];
        ldsm4t(bv, &sV[(kt*16 + (g & 1)*8 + r)*40 + (g >> 1)*8]);
        mma16816(o[0], pa, bv);
        mma16816(o[1], pa, bv + 2);
        ldsm4t(bv, &sV[(kt*16 + (g & 1)*8 + r)*40 + 16 + (g >> 1)*8]);
        mma16816(o[2], pa, bv);
        mma16816(o[3], pa, bv + 2);
    }

#pragma unroll
    for (int sel = 0; sel < 2; sel++) {
        int i = w*16 + (lane >> 2) + sel*8;
        if (i < WS2) {
            int tok = tokbase + (i/WS)*HW + (i%WS);
            __nv_bfloat16* po = outA + (size_t)tok*INNER + h*HD + q2;
#pragma unroll
            for (int dt = 0; dt < 4; dt++) {
                __nv_bfloat162 pr = __floats2bfloat162_rn(o[dt][sel*2], o[dt][sel*2 + 1]);
                *(__nv_bfloat162*)(po + dt*8) = pr;
            }
        }
    }
}

// ---------------- launch ----------------
extern "C" void kernel_launch(void* const* d_in, const int* in_sizes, int n_in,
                              void* d_out, int out_size)
{
    const float* x      = (const float*)d_in[0];
    const float* w_qkv  = (const float*)d_in[1];
    const float* w_out  = (const float*)d_in[2];
    const float* b_out  = (const float*)d_in[3];
    const float* pos    = (const float*)d_in[4];
    const float* ln1_g  = (const float*)d_in[5];
    const float* ln1_b  = (const float*)d_in[6];
    const float* ln2_g  = (const float*)d_in[7];
    const float* ln2_b  = (const float*)d_in[8];
    const float* w1     = (const float*)d_in[9];
    const float* b1     = (const float*)d_in[10];
    const float* w2     = (const float*)d_in[11];
    const float* b2     = (const float*)d_in[12];
    float* out = (float*)d_out;

    void *p_qkv, *p_attn, *p_x2;
    void *p_wqkvT, *p_woutT, *p_w1T, *p_w2T, *p_bias;
    cudaGetSymbolAddress(&p_qkv,  g_qkv);
    cudaGetSymbolAddress(&p_attn, g_attn);
    cudaGetSymbolAddress(&p_x2,   g_x2);
    cudaGetSymbolAddress(&p_wqkvT, g_wqkvT);
    cudaGetSymbolAddress(&p_woutT, g_woutT);
    cudaGetSymbolAddress(&p_w1T,   g_w1T);
    cudaGetSymbolAddress(&p_w2T,   g_w2T);
    cudaGetSymbolAddress(&p_bias,  g_bias2);

    static bool attr_done = false;
    if (!attr_done) {
        cudaFuncSetAttribute((const void*)gemm_ares<EPI_QKV, 9, 1, 1>,
                             cudaFuncAttributeMaxDynamicSharedMemorySize, ARES_SMEM);
        cudaFuncSetAttribute((const void*)gemm_ares<EPI_PROJ, 3, 0, 0>,
                             cudaFuncAttributeMaxDynamicSharedMemorySize, ARES_SMEM);
        cudaFuncSetAttribute((const void*)gemm_mlpfused,
                             cudaFuncAttributeMaxDynamicSharedMemorySize, FUSED_SMEM);
        attr_done = true;
    }

    convert_kernel<<<448, 256>>>(
        w_qkv, w_out, w1, w2, pos,
        (__nv_bfloat16*)p_wqkvT, (__nv_bfloat16*)p_woutT,
        (__nv_bfloat16*)p_w1T, (__nv_bfloat16*)p_w2T, (float*)p_bias);

    // QKV with fused shifted LN1 on A
    gemm_ares<EPI_QKV, 9, 1, 1><<<TOKENS/128, 256, ARES_SMEM>>>(
        nullptr, x, ln1_g, ln1_b,
        (const __nv_bfloat16*)p_wqkvT, 576,
        nullptr, nullptr, nullptr, (__nv_bfloat16*)p_qkv);

    attn_kernel<<<dim3(HEADS, NWIN*NWIN, BATCH), 128>>>(
        (const __nv_bfloat16*)p_qkv, (const float*)p_bias, (__nv_bfloat16*)p_attn);

    // PROJ + back-shift + residual -> x2
    gemm_ares<EPI_PROJ, 3, 0, 0><<<TOKENS/128, 256, ARES_SMEM>>>(
        (const __nv_bfloat16*)p_attn, nullptr, nullptr, nullptr,
        (const __nv_bfloat16*)p_woutT, DIM,
        b_out, x, (float*)p_x2, nullptr);

    // fused MLP: out = gelu(LN2(x2)@w1+b1)@w2 + b2 + x2
    gemm_mlpfused<<<TOKENS/64, 256, FUSED_SMEM>>>(
        (const float*)p_x2, ln2_g, ln2_b,
        (const __nv_bfloat16*)p_w1T, b1,
        (const __nv_bfloat16*)p_w2T, b2, out);
}